// round 14
// baseline (speedup 1.0000x reference)
#include <cuda_runtime.h>
#include <cuda_bf16.h>
#include <cuda_fp16.h>
#include <math.h>
#include <stdint.h>

// Problem constants
#define BSZ 32
#define TX  64
#define TY  64
#define DD  512
#define HH  512
#define G4  2048   // 4*H
#define VV  32000

#define NCTA 128   // persistent LSTM CTAs
#define NTHR 256

// ---------------- scratch (device globals; no allocation allowed) ----------------
__device__ float g_pre_enc[TX * BSZ * G4];
__device__ float g_pre_dec[TY * BSZ * G4];
__device__ float g_hbuf[2][BSZ * HH];
__device__ float g_hs[BSZ * TY * HH];
// Distributed barrier: 32 counters per step, spaced 64 u32 (256B) apart.
__device__ unsigned g_scnt[(TX + TY) * 2048];
__device__ int g_map[BSZ * TY];        // compact row -> original (b*64+t), -1 = pad
__device__ int g_nvalid;               // number of valid decoder rows

// bf16 3-term operands for the pre-activation GEMMs (K-major, K=512)
__device__ __nv_bfloat16 g_WeT_hi[G4 * DD], g_WeT_lo[G4 * DD];
__device__ __nv_bfloat16 g_WdT_hi[G4 * DD], g_WdT_lo[G4 * DD];
__device__ __nv_bfloat16 g_Ae_hi[TX * BSZ * DD], g_Ae_lo[TX * BSZ * DD];
__device__ __nv_bfloat16 g_Ad_hi[TY * BSZ * DD], g_Ad_lo[TY * BSZ * DD];

// fp16 2-term operands for the projection GEMM
__device__ __half g_Bt_h[VV * DD];
__device__ __half g_Ah_hi[BSZ * TY * DD], g_Ah_lo[BSZ * TY * DD];

// ======================= helpers =======================
__device__ __forceinline__ uint32_t smem_u32(const void* p) {
    uint32_t a;
    asm("{ .reg .u64 t; cvta.to.shared.u64 t, %1; cvt.u32.u64 %0, t; }" : "=r"(a) : "l"(p));
    return a;
}

#define LDSM4(r, addr) \
    asm volatile("ldmatrix.sync.aligned.m8n8.x4.shared.b16 {%0,%1,%2,%3}, [%4];" \
        : "=r"((r)[0]), "=r"((r)[1]), "=r"((r)[2]), "=r"((r)[3]) : "r"(addr))

#define MMA_BF16(d, a, b0, b1) \
    asm volatile("mma.sync.aligned.m16n8k16.row.col.f32.bf16.bf16.f32 " \
        "{%0,%1,%2,%3}, {%4,%5,%6,%7}, {%8,%9}, {%0,%1,%2,%3};" \
        : "+f"((d)[0]), "+f"((d)[1]), "+f"((d)[2]), "+f"((d)[3]) \
        : "r"((a)[0]), "r"((a)[1]), "r"((a)[2]), "r"((a)[3]), "r"(b0), "r"(b1))

#define MMA_F16(d, a, b0, b1) \
    asm volatile("mma.sync.aligned.m16n8k16.row.col.f32.f16.f16.f32 " \
        "{%0,%1,%2,%3}, {%4,%5,%6,%7}, {%8,%9}, {%0,%1,%2,%3};" \
        : "+f"((d)[0]), "+f"((d)[1]), "+f"((d)[2]), "+f"((d)[3]) \
        : "r"((a)[0]), "r"((a)[1]), "r"((a)[2]), "r"((a)[3]), "r"(b0), "r"(b1))

#define CP_ASYNC16(dst, src) \
    asm volatile("cp.async.cg.shared.global [%0], [%1], 16;" :: "r"(dst), "l"(src))
#define CP_COMMIT()  asm volatile("cp.async.commit_group;" ::: "memory")
#define CP_WAIT(n)   asm volatile("cp.async.wait_group %0;" :: "n"(n) : "memory")

// packed f32x2 FMA (Blackwell base ISA)
__device__ __forceinline__ void fma2(uint64_t& d, uint64_t a, uint64_t b) {
    asm("fma.rn.f32x2 %0, %1, %2, %0;" : "+l"(d) : "l"(a), "l"(b));
}
__device__ __forceinline__ float pairsum(uint64_t v) {
    return __uint_as_float((uint32_t)v) + __uint_as_float((uint32_t)(v >> 32));
}

// =====================================================================
// Fused init: zero h state + the used barrier counters; block 0 builds
// the compact map. (Used counters: step sigma, slot j -> sigma*2048+j*64.)
// =====================================================================
__global__ void zero_init(float* __restrict__ hbuf, unsigned* __restrict__ scnt,
                          const int* __restrict__ len_dec,
                          int* __restrict__ map, int* __restrict__ nvalid)
{
    const int i = blockIdx.x * 256 + threadIdx.x;
    if (i < BSZ * HH) hbuf[i] = 0.f;
    if (i < (TX + TY) * 32) scnt[(i >> 5) * 2048 + (i & 31) * 64] = 0u;

    if (blockIdx.x == 0) {
        __shared__ int off[BSZ];
        const int tid = threadIdx.x;
        if (tid == 0) {
            int acc = 0;
            for (int b = 0; b < BSZ; b++) {
                off[b] = acc;
                int L = len_dec[b];
                if (L < 0) L = 0;
                if (L > TY) L = TY;
                acc += L;
            }
            *nvalid = acc;
        }
        __syncthreads();
        for (int j = tid; j < BSZ * TY; j += 256) map[j] = -1;
        __syncthreads();
        for (int b = 0; b < BSZ; b++) {
            int L = len_dec[b];
            if (L > TY) L = TY;
            for (int t = tid; t < L; t += 256)
                map[off[b] + t] = b * TY + t;
        }
    }
}

// =====================================================================
// Fused prep: z=0,1 -> Wx transpose+split (enc/dec); z=2,3 -> embedding
// gather+split (enc/dec). grid (4096, 1, 4).
// =====================================================================
__global__ void prep(const float* __restrict__ enc_W, const float* __restrict__ dec_W,
                     __nv_bfloat16* __restrict__ WeT_hi, __nv_bfloat16* __restrict__ WeT_lo,
                     __nv_bfloat16* __restrict__ WdT_hi, __nv_bfloat16* __restrict__ WdT_lo,
                     const float* __restrict__ E,
                     const int* __restrict__ idsE, const int* __restrict__ idsD,
                     __nv_bfloat16* __restrict__ Ae_hi, __nv_bfloat16* __restrict__ Ae_lo,
                     __nv_bfloat16* __restrict__ Ad_hi, __nv_bfloat16* __restrict__ Ad_lo)
{
    const int z = blockIdx.z;
    if (z < 2) {
        if (blockIdx.x >= (G4 / 32) * (DD / 32)) return;   // 64*16 = 1024 tiles
        const float* src = z ? dec_W : enc_W;
        __nv_bfloat16* hi = z ? WdT_hi : WeT_hi;
        __nv_bfloat16* lo = z ? WdT_lo : WeT_lo;

        __shared__ float t[32][33];
        const int tx = threadIdx.x & 31, ty = threadIdx.x >> 5;
        const int bx = blockIdx.x & 63, by = blockIdx.x >> 6;
        const int n = bx * 32 + tx;
        const int kb = by * 32;
#pragma unroll
        for (int r = 0; r < 32; r += 8)
            t[ty + r][tx] = src[(size_t)(kb + ty + r) * G4 + n];
        __syncthreads();
#pragma unroll
        for (int r = 0; r < 32; r += 8) {
            const int nn = bx * 32 + ty + r;
            const int kk = kb + tx;
            const float v = t[tx][ty + r];
            const __nv_bfloat16 h = __float2bfloat16(v);
            hi[(size_t)nn * DD + kk] = h;
            lo[(size_t)nn * DD + kk] = __float2bfloat16(v - __bfloat162float(h));
        }
    } else {
        const int* ids = (z == 3) ? idsD : idsE;
        __nv_bfloat16* hi = (z == 3) ? Ad_hi : Ae_hi;
        __nv_bfloat16* lo = (z == 3) ? Ad_lo : Ae_lo;
        const int idxT = (z == 3) ? TY : TX;

        const int i = blockIdx.x * 256 + threadIdx.x;
        const int row = i >> 9, k = i & 511;
        const int b = row & 31, t = row >> 5;
        const float v = E[(size_t)ids[b * idxT + t] * DD + k];
        const __nv_bfloat16 h = __float2bfloat16(v);
        hi[i] = h;
        lo[i] = __float2bfloat16(v - __bfloat162float(h));
    }
}

// =====================================================================
// Fused 3-term split-bf16 GEMM for BOTH pre-activations (z = 0 enc, 1 dec)
// =====================================================================
__global__ __launch_bounds__(256, 1)
void mma_gemm_pre(const __nv_bfloat16* __restrict__ AhiE, const __nv_bfloat16* __restrict__ AloE,
                  const __nv_bfloat16* __restrict__ BhiE, const __nv_bfloat16* __restrict__ BloE,
                  const float* __restrict__ biasE, float* __restrict__ CE,
                  const __nv_bfloat16* __restrict__ AhiD, const __nv_bfloat16* __restrict__ AloD,
                  const __nv_bfloat16* __restrict__ BhiD, const __nv_bfloat16* __restrict__ BloD,
                  const float* __restrict__ biasD, float* __restrict__ CD)
{
    const __nv_bfloat16* Ahi = blockIdx.z ? AhiD : AhiE;
    const __nv_bfloat16* Alo = blockIdx.z ? AloD : AloE;
    const __nv_bfloat16* Bhi = blockIdx.z ? BhiD : BhiE;
    const __nv_bfloat16* Blo = blockIdx.z ? BloD : BloE;
    const float* bias = blockIdx.z ? biasD : biasE;
    float* C = blockIdx.z ? CD : CE;
    const int N = G4;

    extern __shared__ char smc[];
    const uint32_t sbase = smem_u32(smc);

    const int tid  = threadIdx.x;
    const int wid  = tid >> 5;
    const int lane = tid & 31;
    const int m0 = blockIdx.x * 128;
    const int n0 = blockIdx.y * 128;
    const int wm = (wid & 3) * 32;
    const int wn = (wid >> 2) * 64;

    const __nv_bfloat16* srcs[4] = { Ahi, Alo, Bhi, Blo };
    const int rb[4] = { m0, m0, n0, n0 };

    uint32_t dsts[4];
    const __nv_bfloat16* gsrc[4][4];
#pragma unroll
    for (int q = 0; q < 4; q++) {
        const int i = tid + q * 256;
        const int r = i >> 3, u = i & 7;
        dsts[q] = (uint32_t)(r * 128 + ((u ^ (r & 7)) << 4));
#pragma unroll
        for (int t4 = 0; t4 < 4; t4++)
            gsrc[t4][q] = srcs[t4] + (size_t)(rb[t4] + r) * DD + u * 8;
    }

    float acc[2][8][4];
#pragma unroll
    for (int mt = 0; mt < 2; mt++)
#pragma unroll
        for (int nt = 0; nt < 8; nt++)
#pragma unroll
            for (int e = 0; e < 4; e++) acc[mt][nt][e] = 0.f;

#pragma unroll
    for (int s = 0; s < 2; s++) {
        const uint32_t sb = sbase + (uint32_t)s * 65536u;
        const int koff = s * 64;
#pragma unroll
        for (int t4 = 0; t4 < 4; t4++)
#pragma unroll
            for (int q = 0; q < 4; q++)
                CP_ASYNC16(sb + t4 * 16384 + dsts[q], gsrc[t4][q] + koff);
        CP_COMMIT();
    }

    const int lrow15 = lane & 15;
    const int lhalf  = lane >> 4;

    int cs = 0;
    for (int it = 0; it < 8; it++) {
        if (it < 7) { CP_WAIT(1); } else { CP_WAIT(0); }
        __syncthreads();

        if (it + 2 < 8) {
            int ps = cs + 2; if (ps >= 3) ps -= 3;
            const uint32_t sb = sbase + (uint32_t)ps * 65536u;
            const int koff = (it + 2) * 64;
#pragma unroll
            for (int t4 = 0; t4 < 4; t4++)
#pragma unroll
                for (int q = 0; q < 4; q++)
                    CP_ASYNC16(sb + t4 * 16384 + dsts[q], gsrc[t4][q] + koff);
            CP_COMMIT();
        }

        const uint32_t B = sbase + (uint32_t)cs * 65536u;

#pragma unroll
        for (int j = 0; j < 4; j++) {
            uint32_t ah[2][4], al[2][4];
            uint32_t bh[4][4], bl[4][4];
#pragma unroll
            for (int mt = 0; mt < 2; mt++) {
                const int row = wm + mt * 16 + lrow15;
                const int unit = j * 2 + lhalf;
                const uint32_t addr = B + row * 128 + (((unit ^ (row & 7))) << 4);
                LDSM4(ah[mt], addr);
                LDSM4(al[mt], addr + 16384);
            }
#pragma unroll
            for (int g = 0; g < 4; g++) {
                const int row = wn + g * 16 + lrow15;
                const int unit = j * 2 + lhalf;
                const uint32_t addr = B + 32768 + row * 128 + (((unit ^ (row & 7))) << 4);
                LDSM4(bh[g], addr);
                LDSM4(bl[g], addr + 16384);
            }
#pragma unroll
            for (int mt = 0; mt < 2; mt++)
#pragma unroll
                for (int nt = 0; nt < 8; nt++) {
                    const int g = nt >> 1, o = nt & 1;
                    MMA_BF16(acc[mt][nt], ah[mt], bh[g][o], bh[g][o + 2]);
                    MMA_BF16(acc[mt][nt], ah[mt], bl[g][o], bl[g][o + 2]);
                    MMA_BF16(acc[mt][nt], al[mt], bh[g][o], bh[g][o + 2]);
                }
        }
        cs++; if (cs == 3) cs = 0;
    }

    const int erow = wm + (lane >> 2);
    const int ec = n0 + wn + (lane & 3) * 2;
#pragma unroll
    for (int mt = 0; mt < 2; mt++) {
        const int r0 = m0 + erow + mt * 16;
#pragma unroll
        for (int nt = 0; nt < 8; nt++) {
            const int col = ec + nt * 8;
            const float b0 = bias[col], b1 = bias[col + 1];
            float* p0 = C + (size_t)r0 * N + col;
            float* p1 = C + (size_t)(r0 + 8) * N + col;
            p0[0] = acc[mt][nt][0] + b0;
            p0[1] = acc[mt][nt][1] + b1;
            p1[0] = acc[mt][nt][2] + b0;
            p1[1] = acc[mt][nt][3] + b1;
        }
    }
}

// =====================================================================
// 2-term split-fp16 GEMM (projection), A rows compacted + scattered out.
// =====================================================================
__global__ __launch_bounds__(256, 1)
void mma_gemm_h2(const __half* __restrict__ Ahi, const __half* __restrict__ Alo,
                 const __half* __restrict__ Bh,
                 float* __restrict__ C, int N,
                 const int* __restrict__ map, const int* __restrict__ nvalidp)
{
    const int m0 = blockIdx.x * 128;
    const int n0 = blockIdx.y * 128;
    if (m0 >= *nvalidp) return;

    extern __shared__ char smc[];
    const uint32_t sbase = smem_u32(smc);

    const int tid  = threadIdx.x;
    const int wid  = tid >> 5;
    const int lane = tid & 31;
    const int wm = (wid & 3) * 32;
    const int wn = (wid >> 2) * 64;

    const __half* srcs[3] = { Ahi, Alo, Bh };
    const int rb[3] = { m0, m0, n0 };

    uint32_t dsts[4];
    const __half* gsrc[3][4];
#pragma unroll
    for (int q = 0; q < 4; q++) {
        const int i = tid + q * 256;
        const int r = i >> 3, u = i & 7;
        dsts[q] = (uint32_t)(r * 128 + ((u ^ (r & 7)) << 4));
#pragma unroll
        for (int t3 = 0; t3 < 3; t3++)
            gsrc[t3][q] = srcs[t3] + (size_t)(rb[t3] + r) * DD + u * 8;
    }

    float acc[2][8][4];
#pragma unroll
    for (int mt = 0; mt < 2; mt++)
#pragma unroll
        for (int nt = 0; nt < 8; nt++)
#pragma unroll
            for (int e = 0; e < 4; e++) acc[mt][nt][e] = 0.f;

#pragma unroll
    for (int s = 0; s < 2; s++) {
        const uint32_t sb = sbase + (uint32_t)s * 49152u;
        const int koff = s * 64;
#pragma unroll
        for (int t3 = 0; t3 < 3; t3++)
#pragma unroll
            for (int q = 0; q < 4; q++)
                CP_ASYNC16(sb + t3 * 16384 + dsts[q], gsrc[t3][q] + koff);
        CP_COMMIT();
    }

    const int lrow15 = lane & 15;
    const int lhalf  = lane >> 4;

    int cs = 0;
    for (int it = 0; it < 8; it++) {
        if (it < 7) { CP_WAIT(1); } else { CP_WAIT(0); }
        __syncthreads();

        if (it + 2 < 8) {
            int ps = cs + 2; if (ps >= 3) ps -= 3;
            const uint32_t sb = sbase + (uint32_t)ps * 49152u;
            const int koff = (it + 2) * 64;
#pragma unroll
            for (int t3 = 0; t3 < 3; t3++)
#pragma unroll
                for (int q = 0; q < 4; q++)
                    CP_ASYNC16(sb + t3 * 16384 + dsts[q], gsrc[t3][q] + koff);
            CP_COMMIT();
        }

        const uint32_t B = sbase + (uint32_t)cs * 49152u;

#pragma unroll
        for (int j = 0; j < 4; j++) {
            uint32_t ah[2][4], al[2][4];
            uint32_t bh[4][4];
#pragma unroll
            for (int mt = 0; mt < 2; mt++) {
                const int row = wm + mt * 16 + lrow15;
                const int unit = j * 2 + lhalf;
                const uint32_t addr = B + row * 128 + (((unit ^ (row & 7))) << 4);
                LDSM4(ah[mt], addr);
                LDSM4(al[mt], addr + 16384);
            }
#pragma unroll
            for (int g = 0; g < 4; g++) {
                const int row = wn + g * 16 + lrow15;
                const int unit = j * 2 + lhalf;
                const uint32_t addr = B + 32768 + row * 128 + (((unit ^ (row & 7))) << 4);
                LDSM4(bh[g], addr);
            }
#pragma unroll
            for (int mt = 0; mt < 2; mt++)
#pragma unroll
                for (int nt = 0; nt < 8; nt++) {
                    const int g = nt >> 1, o = nt & 1;
                    MMA_F16(acc[mt][nt], ah[mt], bh[g][o], bh[g][o + 2]);
                    MMA_F16(acc[mt][nt], al[mt], bh[g][o], bh[g][o + 2]);
                }
        }
        cs++; if (cs == 3) cs = 0;
    }

    const int erow = wm + (lane >> 2);
    const int ec = n0 + wn + (lane & 3) * 2;
#pragma unroll
    for (int mt = 0; mt < 2; mt++) {
        const int r0 = m0 + erow + mt * 16;
        const int r1 = r0 + 8;
        const int o0 = map[r0];
        const int o1 = map[r1];
#pragma unroll
        for (int nt = 0; nt < 8; nt++) {
            const int col = ec + nt * 8;
            if (o0 >= 0) {
                float* p0 = C + (size_t)o0 * N + col;
                p0[0] = acc[mt][nt][0];
                p0[1] = acc[mt][nt][1];
            }
            if (o1 >= 0) {
                float* p1 = C + (size_t)o1 * N + col;
                p1[0] = acc[mt][nt][2];
                p1[1] = acc[mt][nt][3];
            }
        }
    }
}

// Zero only the invalid output rows (t >= len_dec[b]).
__global__ void zero_invalid(const int* __restrict__ len_dec, float* __restrict__ out)
{
    const int row = blockIdx.y;          // b*64 + t
    const int b = row >> 6, t = row & 63;
    if (t < len_dec[b]) return;
    const int i = blockIdx.x * 1024 + threadIdx.x * 4;
    if (i < VV) {
        float4 z = make_float4(0.f, 0.f, 0.f, 0.f);
        *(float4*)(out + (size_t)row * VV + i) = z;
    }
}

// Compact + split hs into fp16 hi/lo.
__global__ void split_compact_f16(const float* __restrict__ src,
                                  const int* __restrict__ map,
                                  __half* __restrict__ hi, __half* __restrict__ lo)
{
    const int i = blockIdx.x * 256 + threadIdx.x;
    const int j = i >> 9, k = i & 511;
    const int s = map[j];
    const float v = (s >= 0) ? src[(size_t)s * DD + k] : 0.f;
    const __half h = __float2half(v);
    hi[i] = h;
    lo[i] = __float2half(v - __half2float(h));
}

// Transpose + single fp16:  src[K=512][VV] f32  ->  h [VV][512] fp16
__global__ void transpose_f16(const float* __restrict__ src, int N,
                              __half* __restrict__ dst)
{
    __shared__ float t[32][33];
    const int tx = threadIdx.x & 31, ty = threadIdx.x >> 5;
    const int n = blockIdx.x * 32 + tx;
    const int kb = blockIdx.y * 32;
#pragma unroll
    for (int r = 0; r < 32; r += 8)
        t[ty + r][tx] = src[(size_t)(kb + ty + r) * N + n];
    __syncthreads();
#pragma unroll
    for (int r = 0; r < 32; r += 8) {
        const int nn = blockIdx.x * 32 + ty + r;
        const int kk = kb + tx;
        dst[(size_t)nn * DD + kk] = __float2half(t[tx][ty + r]);
    }
}

// =====================================================================
// Persistent LSTM — R13 structure; ONLY change: the step barrier uses 32
// distributed counters (c & 31), killing same-address RED serialization.
// =====================================================================
__global__ __launch_bounds__(NTHR, 1)
void lstm_persist(const float* __restrict__ pre_enc, const float* __restrict__ pre_dec,
                  const float* __restrict__ enc_Wh, const float* __restrict__ dec_Wh,
                  const int* __restrict__ len_enc, const int* __restrict__ len_dec,
                  float* __restrict__ hbuf, float* __restrict__ hs,
                  unsigned* __restrict__ scnt)
{
    extern __shared__ float smf[];
    float* whs  = smf;                    // 16*516
    float* hsm  = smf + 16 * 516;         // 32*516
    float* zbuf = hsm + 32 * 516;         // 2 * 544

    const int tid = threadIdx.x;
    const int cta = blockIdx.x;
    const int wid = tid >> 5;
    const int lane = tid & 31;

    // dot decomposition
    const int wk = wid >> 2;
    const int wq = wid & 3;
    const int base_b = (wq & 1) * 16;
    const int base_z = (wq >> 1) * 8;
    const int lb = lane & 7;
    const int lz = lane >> 3;
    const int rb0 = base_b + lb,     rb1 = base_b + 8 + lb;
    const int rz0 = base_z + lz,     rz1 = base_z + 4 + lz;
    const int kof = wk * 256;

    // gate-phase constants (tid < 128)
    const int gb  = tid >> 2;
    const int ghc = tid & 3;
    const int gn  = cta * 4 + ghc;

    float c_reg = 0.f;
    float pzi = 0.f, pzj = 0.f, pzf = 0.f, pzo = 0.f;

    for (int phase = 0; phase < 2; phase++) {
        const float* Wh  = phase ? dec_Wh  : enc_Wh;
        const float* pre = phase ? pre_dec : pre_enc;
        const int*   len = phase ? len_dec : len_enc;

        for (int i = tid; i < 16 * 512; i += NTHR) {
            int z = i >> 9, k = i & 511;
            whs[z * 516 + k] =
                __ldg(&Wh[(size_t)k * G4 + (z >> 2) * 512 + cta * 4 + (z & 3)]);
        }
        const int mylen = (tid < 128) ? len[gb] : 0;

        // prefetch pz for s = 0
        if (tid < 128) {
            const float* pz = pre + (size_t)gb * G4 + gn;
            pzi = __ldg(pz);
            pzj = __ldg(pz + 512);
            pzf = __ldg(pz + 1024);
            pzo = __ldg(pz + 1536);
        }
        __syncthreads();

        for (int s = 0; s < 64; s++) {
            const int sigma = phase * 64 + s;
            const float* hin  = hbuf + (sigma & 1) * (BSZ * HH);
            float*       hout = hbuf + ((sigma + 1) & 1) * (BSZ * HH);

            // Stage h into smem (uniform; fully unrolled for max MLP).
#pragma unroll
            for (int q = 0; q < 16; q++) {
                const int i = tid + q * NTHR;
                const int b = i >> 7, k4 = i & 127;
                float4 v = __ldcg((const float4*)&hin[b * HH + k4 * 4]);
                *(float4*)&hsm[b * 516 + k4 * 4] = v;
            }
            __syncthreads();

            // 2b x 2zc register tile over this warp's k-half.
            {
                const float* A0 = &hsm[rb0 * 516 + kof];
                const float* A1 = &hsm[rb1 * 516 + kof];
                const float* W0 = &whs[rz0 * 516 + kof];
                const float* W1 = &whs[rz1 * 516 + kof];
                uint64_t a00 = 0, a01 = 0, a10 = 0, a11 = 0;
#pragma unroll 4
                for (int k = 0; k < 256; k += 4) {
                    const ulonglong2 va0 = *(const ulonglong2*)(A0 + k);
                    const ulonglong2 va1 = *(const ulonglong2*)(A1 + k);
                    const ulonglong2 vw0 = *(const ulonglong2*)(W0 + k);
                    const ulonglong2 vw1 = *(const ulonglong2*)(W1 + k);
                    fma2(a00, va0.x, vw0.x); fma2(a00, va0.y, vw0.y);
                    fma2(a01, va0.x, vw1.x); fma2(a01, va0.y, vw1.y);
                    fma2(a10, va1.x, vw0.x); fma2(a10, va1.y, vw0.y);
                    fma2(a11, va1.x, vw1.x); fma2(a11, va1.y, vw1.y);
                }
                float* zb = zbuf + wk * 544;
                zb[rb0 * 17 + rz0] = pairsum(a00);
                zb[rb0 * 17 + rz1] = pairsum(a01);
                zb[rb1 * 17 + rz0] = pairsum(a10);
                zb[rb1 * 17 + rz1] = pairsum(a11);
            }
            __syncthreads();

            if (tid < 128) {
                const int zi0 = gb * 17 + ghc;
                float zi = pzi + zbuf[zi0]      + zbuf[544 + zi0];
                float zj = pzj + zbuf[zi0 + 4]  + zbuf[544 + zi0 + 4];
                float zf = pzf + zbuf[zi0 + 8]  + zbuf[544 + zi0 + 8];
                float zo = pzo + zbuf[zi0 + 12] + zbuf[544 + zi0 + 12];

                float fg = 1.f / (1.f + expf(-(zf + 1.0f)));   // forget bias 1.0
                float ig = 1.f / (1.f + expf(-zi));
                float og = 1.f / (1.f + expf(-zo));
                float cn = c_reg * fg + ig * tanhf(zj);
                float hn = tanhf(cn) * og;

                bool m = (s < mylen);
                float hprev = hsm[gb * 516 + gn];
                c_reg = m ? cn : c_reg;
                hout[gb * HH + gn] = m ? hn : hprev;
                if (phase)
                    hs[((size_t)gb * TY + s) * HH + gn] = m ? hn : 0.f;
            }
            __syncthreads();   // all h stores issued before arrival

            // prefetch pz for step s+1 (off the post-barrier critical path)
            if (tid < 128 && s + 1 < 64) {
                const float* pz = pre + (size_t)(s + 1) * BSZ * G4 + (size_t)gb * G4 + gn;
                pzi = __ldg(pz);
                pzj = __ldg(pz + 512);
                pzf = __ldg(pz + 1024);
                pzo = __ldg(pz + 1536);
            }

            // Distributed barrier: RED own slot counter (4 CTAs/counter),
            // warp0 lanes poll all 32 counters until each reaches 4.
            {
                unsigned* cbase = scnt + (size_t)sigma * 2048;
                if (tid == 0) {
                    asm volatile("red.release.gpu.global.add.u32 [%0], 1;"
                                 :: "l"(cbase + (cta & 31) * 64) : "memory");
                }
                if (wid == 0) {
                    unsigned* myc = cbase + lane * 64;
                    unsigned v;
                    do {
                        asm volatile("ld.relaxed.gpu.global.u32 %0, [%1];"
                                     : "=r"(v) : "l"(myc) : "memory");
                    } while (__any_sync(0xffffffffu, v < 4u));
                    asm volatile("ld.acquire.gpu.global.u32 %0, [%1];"
                                 : "=r"(v) : "l"(myc) : "memory");
                }
            }
            __syncthreads();   // propagate warp0's acquires to the CTA
        }
    }
}

// =====================================================================
// Host launcher (graph-capturable). lstm_persist stays the 4th kernel.
// =====================================================================
extern "C" void kernel_launch(void* const* d_in, const int* in_sizes, int n_in,
                              void* d_out, int out_size)
{
    const int*   enc_ids = (const int*)d_in[0];
    const int*   dec_ids = (const int*)d_in[1];
    const int*   len_enc = (const int*)d_in[2];
    const int*   len_dec = (const int*)d_in[3];
    const float* E       = (const float*)d_in[4];
    const float* enc_W   = (const float*)d_in[5];
    const float* enc_b   = (const float*)d_in[6];
    const float* dec_W   = (const float*)d_in[7];
    const float* dec_b   = (const float*)d_in[8];
    const float* proj_W  = (const float*)d_in[9];
    float*       out     = (float*)d_out;

    float *pre_enc, *pre_dec, *hbuf, *hs;
    unsigned* scnt;
    int *map, *nvalid;
    cudaGetSymbolAddress((void**)&pre_enc, g_pre_enc);
    cudaGetSymbolAddress((void**)&pre_dec, g_pre_dec);
    cudaGetSymbolAddress((void**)&hbuf,    g_hbuf);
    cudaGetSymbolAddress((void**)&hs,      g_hs);
    cudaGetSymbolAddress((void**)&scnt,    g_scnt);
    cudaGetSymbolAddress((void**)&map,     g_map);
    cudaGetSymbolAddress((void**)&nvalid,  g_nvalid);

    __nv_bfloat16 *WeT_hi, *WeT_lo, *WdT_hi, *WdT_lo;
    __nv_bfloat16 *Ae_hi, *Ae_lo, *Ad_hi, *Ad_lo;
    __half *Bt_h, *Ah_hi, *Ah_lo;
    cudaGetSymbolAddress((void**)&WeT_hi, g_WeT_hi);
    cudaGetSymbolAddress((void**)&WeT_lo, g_WeT_lo);
    cudaGetSymbolAddress((void**)&WdT_hi, g_WdT_hi);
    cudaGetSymbolAddress((void**)&WdT_lo, g_WdT_lo);
    cudaGetSymbolAddress((void**)&Ae_hi,  g_Ae_hi);
    cudaGetSymbolAddress((void**)&Ae_lo,  g_Ae_lo);
    cudaGetSymbolAddress((void**)&Ad_hi,  g_Ad_hi);
    cudaGetSymbolAddress((void**)&Ad_lo,  g_Ad_lo);
    cudaGetSymbolAddress((void**)&Bt_h,   g_Bt_h);
    cudaGetSymbolAddress((void**)&Ah_hi,  g_Ah_hi);
    cudaGetSymbolAddress((void**)&Ah_lo,  g_Ah_lo);

    const size_t lstm_smem  = (16 * 516 + 32 * 516 + 2 * 544) * sizeof(float);
    const size_t gemm_smem  = 3 * 4 * 16384;   // 192KB (bf16 3-term)
    const size_t gemm2_smem = 3 * 3 * 16384;   // 144KB (fp16 2-term)
    static bool attr_set = false;
    if (!attr_set) {
        cudaFuncSetAttribute(lstm_persist,
                             cudaFuncAttributeMaxDynamicSharedMemorySize, (int)lstm_smem);
        cudaFuncSetAttribute(mma_gemm_pre,
                             cudaFuncAttributeMaxDynamicSharedMemorySize, (int)gemm_smem);
        cudaFuncSetAttribute(mma_gemm_h2,
                             cudaFuncAttributeMaxDynamicSharedMemorySize, (int)gemm2_smem);
        attr_set = true;
    }

    // (1) zero h + barrier counters; build compact map (block 0)
    zero_init<<<64, 256>>>(hbuf, scnt, len_dec, map, nvalid);

    // (2) fused Wx transposes + embedding gathers
    prep<<<dim3(4096, 1, 4), 256>>>(enc_W, dec_W, WeT_hi, WeT_lo, WdT_hi, WdT_lo,
                                    E, enc_ids, dec_ids,
                                    Ae_hi, Ae_lo, Ad_hi, Ad_lo);

    // (3) fused pre-activation GEMMs (enc & dec)
    mma_gemm_pre<<<dim3(16, G4 / 128, 2), 256, gemm_smem>>>(
        Ae_hi, Ae_lo, WeT_hi, WeT_lo, enc_b, pre_enc,
        Ad_hi, Ad_lo, WdT_hi, WdT_lo, dec_b, pre_dec);

    // (4) full recurrence — profiled launch
    lstm_persist<<<NCTA, NTHR, lstm_smem>>>(
        pre_enc, pre_dec,
        enc_W + (size_t)DD * G4, dec_W + (size_t)DD * G4,
        len_enc, len_dec, hbuf, hs, scnt);

    // (5..) zero invalid output rows, then the projection chain
    zero_invalid<<<dim3(32, BSZ * TY), 256>>>(len_dec, out);
    transpose_f16<<<dim3(VV / 32, DD / 32), 256>>>(proj_W, VV, Bt_h);
    split_compact_f16<<<(BSZ * TY * DD) / 256, 256>>>(hs, map, Ah_hi, Ah_lo);
    mma_gemm_h2<<<dim3(16, VV / 128), 256, gemm2_smem>>>(Ah_hi, Ah_lo, Bt_h,
                                                         out, VV, map, nvalid);
}

// round 15
// speedup vs baseline: 1.1455x; 1.1455x over previous
#include <cuda_runtime.h>
#include <cuda_bf16.h>
#include <cuda_fp16.h>
#include <math.h>
#include <stdint.h>

// Problem constants
#define BSZ 32
#define TX  64
#define TY  64
#define DD  512
#define HH  512
#define G4  2048   // 4*H
#define VV  32000

#define NCTA 128   // persistent LSTM CTAs
#define NTHR 256

// ---------------- scratch (device globals; no allocation allowed) ----------------
__device__ float g_pre_enc[TX * BSZ * G4];
__device__ float g_pre_dec[TY * BSZ * G4];
__device__ float g_hbuf[2][BSZ * HH];
__device__ float g_hs[BSZ * TY * HH];
__device__ unsigned g_scnt[TX + TY];   // per-step arrival counters
__device__ int g_map[BSZ * TY];        // compact row -> original (b*64+t), -1 = pad
__device__ int g_nvalid;               // number of valid decoder rows

// bf16 3-term operands for the pre-activation GEMMs (K-major, K=512)
__device__ __nv_bfloat16 g_WeT_hi[G4 * DD], g_WeT_lo[G4 * DD];
__device__ __nv_bfloat16 g_WdT_hi[G4 * DD], g_WdT_lo[G4 * DD];
__device__ __nv_bfloat16 g_Ae_hi[TX * BSZ * DD], g_Ae_lo[TX * BSZ * DD];
__device__ __nv_bfloat16 g_Ad_hi[TY * BSZ * DD], g_Ad_lo[TY * BSZ * DD];

// fp16 1-term operands for the projection GEMM
__device__ __half g_Bt_h[VV * DD];
__device__ __half g_Ah_h[BSZ * TY * DD];

// ======================= helpers =======================
__device__ __forceinline__ uint32_t smem_u32(const void* p) {
    uint32_t a;
    asm("{ .reg .u64 t; cvta.to.shared.u64 t, %1; cvt.u32.u64 %0, t; }" : "=r"(a) : "l"(p));
    return a;
}

#define LDSM4(r, addr) \
    asm volatile("ldmatrix.sync.aligned.m8n8.x4.shared.b16 {%0,%1,%2,%3}, [%4];" \
        : "=r"((r)[0]), "=r"((r)[1]), "=r"((r)[2]), "=r"((r)[3]) : "r"(addr))

#define MMA_BF16(d, a, b0, b1) \
    asm volatile("mma.sync.aligned.m16n8k16.row.col.f32.bf16.bf16.f32 " \
        "{%0,%1,%2,%3}, {%4,%5,%6,%7}, {%8,%9}, {%0,%1,%2,%3};" \
        : "+f"((d)[0]), "+f"((d)[1]), "+f"((d)[2]), "+f"((d)[3]) \
        : "r"((a)[0]), "r"((a)[1]), "r"((a)[2]), "r"((a)[3]), "r"(b0), "r"(b1))

#define MMA_F16(d, a, b0, b1) \
    asm volatile("mma.sync.aligned.m16n8k16.row.col.f32.f16.f16.f32 " \
        "{%0,%1,%2,%3}, {%4,%5,%6,%7}, {%8,%9}, {%0,%1,%2,%3};" \
        : "+f"((d)[0]), "+f"((d)[1]), "+f"((d)[2]), "+f"((d)[3]) \
        : "r"((a)[0]), "r"((a)[1]), "r"((a)[2]), "r"((a)[3]), "r"(b0), "r"(b1))

#define CP_ASYNC16(dst, src) \
    asm volatile("cp.async.cg.shared.global [%0], [%1], 16;" :: "r"(dst), "l"(src))
#define CP_COMMIT()  asm volatile("cp.async.commit_group;" ::: "memory")
#define CP_WAIT(n)   asm volatile("cp.async.wait_group %0;" :: "n"(n) : "memory")

// packed f32x2 FMA (Blackwell base ISA)
__device__ __forceinline__ void fma2(uint64_t& d, uint64_t a, uint64_t b) {
    asm("fma.rn.f32x2 %0, %1, %2, %0;" : "+l"(d) : "l"(a), "l"(b));
}
__device__ __forceinline__ float pairsum(uint64_t v) {
    return __uint_as_float((uint32_t)v) + __uint_as_float((uint32_t)(v >> 32));
}

// =====================================================================
// Fused init: zero h state + step counters; block 0 builds the compact map.
// =====================================================================
__global__ void zero_init(float* __restrict__ hbuf, unsigned* __restrict__ scnt,
                          const int* __restrict__ len_dec,
                          int* __restrict__ map, int* __restrict__ nvalid)
{
    const int i = blockIdx.x * 256 + threadIdx.x;
    if (i < BSZ * HH) hbuf[i] = 0.f;
    if (i < TX + TY)  scnt[i] = 0u;

    if (blockIdx.x == 0) {
        __shared__ int off[BSZ];
        const int tid = threadIdx.x;
        if (tid == 0) {
            int acc = 0;
            for (int b = 0; b < BSZ; b++) {
                off[b] = acc;
                int L = len_dec[b];
                if (L < 0) L = 0;
                if (L > TY) L = TY;
                acc += L;
            }
            *nvalid = acc;
        }
        __syncthreads();
        for (int j = tid; j < BSZ * TY; j += 256) map[j] = -1;
        __syncthreads();
        for (int b = 0; b < BSZ; b++) {
            int L = len_dec[b];
            if (L > TY) L = TY;
            for (int t = tid; t < L; t += 256)
                map[off[b] + t] = b * TY + t;
        }
    }
}

// =====================================================================
// Fused prep: z=0,1 -> Wx transpose+split (enc/dec); z=2,3 -> embedding
// gather+split (enc/dec). grid (4096, 1, 4).
// =====================================================================
__global__ void prep(const float* __restrict__ enc_W, const float* __restrict__ dec_W,
                     __nv_bfloat16* __restrict__ WeT_hi, __nv_bfloat16* __restrict__ WeT_lo,
                     __nv_bfloat16* __restrict__ WdT_hi, __nv_bfloat16* __restrict__ WdT_lo,
                     const float* __restrict__ E,
                     const int* __restrict__ idsE, const int* __restrict__ idsD,
                     __nv_bfloat16* __restrict__ Ae_hi, __nv_bfloat16* __restrict__ Ae_lo,
                     __nv_bfloat16* __restrict__ Ad_hi, __nv_bfloat16* __restrict__ Ad_lo)
{
    const int z = blockIdx.z;
    if (z < 2) {
        if (blockIdx.x >= (G4 / 32) * (DD / 32)) return;   // 64*16 = 1024 tiles
        const float* src = z ? dec_W : enc_W;
        __nv_bfloat16* hi = z ? WdT_hi : WeT_hi;
        __nv_bfloat16* lo = z ? WdT_lo : WeT_lo;

        __shared__ float t[32][33];
        const int tx = threadIdx.x & 31, ty = threadIdx.x >> 5;
        const int bx = blockIdx.x & 63, by = blockIdx.x >> 6;
        const int n = bx * 32 + tx;
        const int kb = by * 32;
#pragma unroll
        for (int r = 0; r < 32; r += 8)
            t[ty + r][tx] = src[(size_t)(kb + ty + r) * G4 + n];
        __syncthreads();
#pragma unroll
        for (int r = 0; r < 32; r += 8) {
            const int nn = bx * 32 + ty + r;
            const int kk = kb + tx;
            const float v = t[tx][ty + r];
            const __nv_bfloat16 h = __float2bfloat16(v);
            hi[(size_t)nn * DD + kk] = h;
            lo[(size_t)nn * DD + kk] = __float2bfloat16(v - __bfloat162float(h));
        }
    } else {
        const int* ids = (z == 3) ? idsD : idsE;
        __nv_bfloat16* hi = (z == 3) ? Ad_hi : Ae_hi;
        __nv_bfloat16* lo = (z == 3) ? Ad_lo : Ae_lo;
        const int idxT = (z == 3) ? TY : TX;

        const int i = blockIdx.x * 256 + threadIdx.x;
        const int row = i >> 9, k = i & 511;
        const int b = row & 31, t = row >> 5;
        const float v = E[(size_t)ids[b * idxT + t] * DD + k];
        const __nv_bfloat16 h = __float2bfloat16(v);
        hi[i] = h;
        lo[i] = __float2bfloat16(v - __bfloat162float(h));
    }
}

// =====================================================================
// Fused 3-term split-bf16 GEMM for BOTH pre-activations (z = 0 enc, 1 dec)
// =====================================================================
__global__ __launch_bounds__(256, 1)
void mma_gemm_pre(const __nv_bfloat16* __restrict__ AhiE, const __nv_bfloat16* __restrict__ AloE,
                  const __nv_bfloat16* __restrict__ BhiE, const __nv_bfloat16* __restrict__ BloE,
                  const float* __restrict__ biasE, float* __restrict__ CE,
                  const __nv_bfloat16* __restrict__ AhiD, const __nv_bfloat16* __restrict__ AloD,
                  const __nv_bfloat16* __restrict__ BhiD, const __nv_bfloat16* __restrict__ BloD,
                  const float* __restrict__ biasD, float* __restrict__ CD)
{
    const __nv_bfloat16* Ahi = blockIdx.z ? AhiD : AhiE;
    const __nv_bfloat16* Alo = blockIdx.z ? AloD : AloE;
    const __nv_bfloat16* Bhi = blockIdx.z ? BhiD : BhiE;
    const __nv_bfloat16* Blo = blockIdx.z ? BloD : BloE;
    const float* bias = blockIdx.z ? biasD : biasE;
    float* C = blockIdx.z ? CD : CE;
    const int N = G4;

    extern __shared__ char smc[];
    const uint32_t sbase = smem_u32(smc);

    const int tid  = threadIdx.x;
    const int wid  = tid >> 5;
    const int lane = tid & 31;
    const int m0 = blockIdx.x * 128;
    const int n0 = blockIdx.y * 128;
    const int wm = (wid & 3) * 32;
    const int wn = (wid >> 2) * 64;

    const __nv_bfloat16* srcs[4] = { Ahi, Alo, Bhi, Blo };
    const int rb[4] = { m0, m0, n0, n0 };

    uint32_t dsts[4];
    const __nv_bfloat16* gsrc[4][4];
#pragma unroll
    for (int q = 0; q < 4; q++) {
        const int i = tid + q * 256;
        const int r = i >> 3, u = i & 7;
        dsts[q] = (uint32_t)(r * 128 + ((u ^ (r & 7)) << 4));
#pragma unroll
        for (int t4 = 0; t4 < 4; t4++)
            gsrc[t4][q] = srcs[t4] + (size_t)(rb[t4] + r) * DD + u * 8;
    }

    float acc[2][8][4];
#pragma unroll
    for (int mt = 0; mt < 2; mt++)
#pragma unroll
        for (int nt = 0; nt < 8; nt++)
#pragma unroll
            for (int e = 0; e < 4; e++) acc[mt][nt][e] = 0.f;

#pragma unroll
    for (int s = 0; s < 2; s++) {
        const uint32_t sb = sbase + (uint32_t)s * 65536u;
        const int koff = s * 64;
#pragma unroll
        for (int t4 = 0; t4 < 4; t4++)
#pragma unroll
            for (int q = 0; q < 4; q++)
                CP_ASYNC16(sb + t4 * 16384 + dsts[q], gsrc[t4][q] + koff);
        CP_COMMIT();
    }

    const int lrow15 = lane & 15;
    const int lhalf  = lane >> 4;

    int cs = 0;
    for (int it = 0; it < 8; it++) {
        if (it < 7) { CP_WAIT(1); } else { CP_WAIT(0); }
        __syncthreads();

        if (it + 2 < 8) {
            int ps = cs + 2; if (ps >= 3) ps -= 3;
            const uint32_t sb = sbase + (uint32_t)ps * 65536u;
            const int koff = (it + 2) * 64;
#pragma unroll
            for (int t4 = 0; t4 < 4; t4++)
#pragma unroll
                for (int q = 0; q < 4; q++)
                    CP_ASYNC16(sb + t4 * 16384 + dsts[q], gsrc[t4][q] + koff);
            CP_COMMIT();
        }

        const uint32_t B = sbase + (uint32_t)cs * 65536u;

#pragma unroll
        for (int j = 0; j < 4; j++) {
            uint32_t ah[2][4], al[2][4];
            uint32_t bh[4][4], bl[4][4];
#pragma unroll
            for (int mt = 0; mt < 2; mt++) {
                const int row = wm + mt * 16 + lrow15;
                const int unit = j * 2 + lhalf;
                const uint32_t addr = B + row * 128 + (((unit ^ (row & 7))) << 4);
                LDSM4(ah[mt], addr);
                LDSM4(al[mt], addr + 16384);
            }
#pragma unroll
            for (int g = 0; g < 4; g++) {
                const int row = wn + g * 16 + lrow15;
                const int unit = j * 2 + lhalf;
                const uint32_t addr = B + 32768 + row * 128 + (((unit ^ (row & 7))) << 4);
                LDSM4(bh[g], addr);
                LDSM4(bl[g], addr + 16384);
            }
#pragma unroll
            for (int mt = 0; mt < 2; mt++)
#pragma unroll
                for (int nt = 0; nt < 8; nt++) {
                    const int g = nt >> 1, o = nt & 1;
                    MMA_BF16(acc[mt][nt], ah[mt], bh[g][o], bh[g][o + 2]);
                    MMA_BF16(acc[mt][nt], ah[mt], bl[g][o], bl[g][o + 2]);
                    MMA_BF16(acc[mt][nt], al[mt], bh[g][o], bh[g][o + 2]);
                }
        }
        cs++; if (cs == 3) cs = 0;
    }

    const int erow = wm + (lane >> 2);
    const int ec = n0 + wn + (lane & 3) * 2;
#pragma unroll
    for (int mt = 0; mt < 2; mt++) {
        const int r0 = m0 + erow + mt * 16;
#pragma unroll
        for (int nt = 0; nt < 8; nt++) {
            const int col = ec + nt * 8;
            const float b0 = bias[col], b1 = bias[col + 1];
            float* p0 = C + (size_t)r0 * N + col;
            float* p1 = C + (size_t)(r0 + 8) * N + col;
            p0[0] = acc[mt][nt][0] + b0;
            p0[1] = acc[mt][nt][1] + b1;
            p1[0] = acc[mt][nt][2] + b0;
            p1[1] = acc[mt][nt][3] + b1;
        }
    }
}

// =====================================================================
// 1-term fp16 GEMM (projection): C = fp16(A) @ fp16(B)^T.
// 2 operand tiles (32KB/stage), 3-stage pipeline. A rows compacted:
// CTAs past *nvalidp exit; outputs scatter through map (-1 skipped).
// =====================================================================
__global__ __launch_bounds__(256, 1)
void mma_gemm_h1(const __half* __restrict__ Ah, const __half* __restrict__ Bh,
                 float* __restrict__ C, int N,
                 const int* __restrict__ map, const int* __restrict__ nvalidp)
{
    const int m0 = blockIdx.x * 128;
    const int n0 = blockIdx.y * 128;
    if (m0 >= *nvalidp) return;

    extern __shared__ char smc[];
    const uint32_t sbase = smem_u32(smc);

    const int tid  = threadIdx.x;
    const int wid  = tid >> 5;
    const int lane = tid & 31;
    const int wm = (wid & 3) * 32;
    const int wn = (wid >> 2) * 64;

    const __half* srcs[2] = { Ah, Bh };
    const int rb[2] = { m0, n0 };

    uint32_t dsts[4];
    const __half* gsrc[2][4];
#pragma unroll
    for (int q = 0; q < 4; q++) {
        const int i = tid + q * 256;
        const int r = i >> 3, u = i & 7;
        dsts[q] = (uint32_t)(r * 128 + ((u ^ (r & 7)) << 4));
#pragma unroll
        for (int t2 = 0; t2 < 2; t2++)
            gsrc[t2][q] = srcs[t2] + (size_t)(rb[t2] + r) * DD + u * 8;
    }

    float acc[2][8][4];
#pragma unroll
    for (int mt = 0; mt < 2; mt++)
#pragma unroll
        for (int nt = 0; nt < 8; nt++)
#pragma unroll
            for (int e = 0; e < 4; e++) acc[mt][nt][e] = 0.f;

    // stage stride = 2 tiles x 16KB = 32KB
#pragma unroll
    for (int s = 0; s < 2; s++) {
        const uint32_t sb = sbase + (uint32_t)s * 32768u;
        const int koff = s * 64;
#pragma unroll
        for (int t2 = 0; t2 < 2; t2++)
#pragma unroll
            for (int q = 0; q < 4; q++)
                CP_ASYNC16(sb + t2 * 16384 + dsts[q], gsrc[t2][q] + koff);
        CP_COMMIT();
    }

    const int lrow15 = lane & 15;
    const int lhalf  = lane >> 4;

    int cs = 0;
    for (int it = 0; it < 8; it++) {
        if (it < 7) { CP_WAIT(1); } else { CP_WAIT(0); }
        __syncthreads();

        if (it + 2 < 8) {
            int ps = cs + 2; if (ps >= 3) ps -= 3;
            const uint32_t sb = sbase + (uint32_t)ps * 32768u;
            const int koff = (it + 2) * 64;
#pragma unroll
            for (int t2 = 0; t2 < 2; t2++)
#pragma unroll
                for (int q = 0; q < 4; q++)
                    CP_ASYNC16(sb + t2 * 16384 + dsts[q], gsrc[t2][q] + koff);
            CP_COMMIT();
        }

        const uint32_t B = sbase + (uint32_t)cs * 32768u;

#pragma unroll
        for (int j = 0; j < 4; j++) {
            uint32_t ah[2][4];
            uint32_t bh[4][4];
#pragma unroll
            for (int mt = 0; mt < 2; mt++) {
                const int row = wm + mt * 16 + lrow15;
                const int unit = j * 2 + lhalf;
                LDSM4(ah[mt], B + row * 128 + (((unit ^ (row & 7))) << 4));
            }
#pragma unroll
            for (int g = 0; g < 4; g++) {
                const int row = wn + g * 16 + lrow15;
                const int unit = j * 2 + lhalf;
                LDSM4(bh[g], B + 16384 + row * 128 + (((unit ^ (row & 7))) << 4));
            }
#pragma unroll
            for (int mt = 0; mt < 2; mt++)
#pragma unroll
                for (int nt = 0; nt < 8; nt++) {
                    const int g = nt >> 1, o = nt & 1;
                    MMA_F16(acc[mt][nt], ah[mt], bh[g][o], bh[g][o + 2]);
                }
        }
        cs++; if (cs == 3) cs = 0;
    }

    const int erow = wm + (lane >> 2);
    const int ec = n0 + wn + (lane & 3) * 2;
#pragma unroll
    for (int mt = 0; mt < 2; mt++) {
        const int r0 = m0 + erow + mt * 16;
        const int r1 = r0 + 8;
        const int o0 = map[r0];
        const int o1 = map[r1];
#pragma unroll
        for (int nt = 0; nt < 8; nt++) {
            const int col = ec + nt * 8;
            if (o0 >= 0) {
                float* p0 = C + (size_t)o0 * N + col;
                p0[0] = acc[mt][nt][0];
                p0[1] = acc[mt][nt][1];
            }
            if (o1 >= 0) {
                float* p1 = C + (size_t)o1 * N + col;
                p1[0] = acc[mt][nt][2];
                p1[1] = acc[mt][nt][3];
            }
        }
    }
}

// Zero only the invalid output rows (t >= len_dec[b]).
__global__ void zero_invalid(const int* __restrict__ len_dec, float* __restrict__ out)
{
    const int row = blockIdx.y;          // b*64 + t
    const int b = row >> 6, t = row & 63;
    if (t < len_dec[b]) return;
    const int i = blockIdx.x * 1024 + threadIdx.x * 4;
    if (i < VV) {
        float4 z = make_float4(0.f, 0.f, 0.f, 0.f);
        *(float4*)(out + (size_t)row * VV + i) = z;
    }
}

// Compact hs into fp16 (single term).
__global__ void compact_f16(const float* __restrict__ src,
                            const int* __restrict__ map,
                            __half* __restrict__ dst)
{
    const int i = blockIdx.x * 256 + threadIdx.x;
    const int j = i >> 9, k = i & 511;
    const int s = map[j];
    const float v = (s >= 0) ? src[(size_t)s * DD + k] : 0.f;
    dst[i] = __float2half(v);
}

// Transpose + fp16:  src[K=512][VV] f32  ->  h [VV][512] fp16
__global__ void transpose_f16(const float* __restrict__ src, int N,
                              __half* __restrict__ dst)
{
    __shared__ float t[32][33];
    const int tx = threadIdx.x & 31, ty = threadIdx.x >> 5;
    const int n = blockIdx.x * 32 + tx;
    const int kb = blockIdx.y * 32;
#pragma unroll
    for (int r = 0; r < 32; r += 8)
        t[ty + r][tx] = src[(size_t)(kb + ty + r) * N + n];
    __syncthreads();
#pragma unroll
    for (int r = 0; r < 32; r += 8) {
        const int nn = blockIdx.x * 32 + ty + r;
        const int kk = kb + tx;
        dst[(size_t)nn * DD + kk] = __float2half(t[tx][ty + r]);
    }
}

// =====================================================================
// Persistent LSTM — PROVEN R13 version verbatim (single-counter barrier,
// uniform staging, 2b x 2zc f32x2 dot, pz prefetch before the barrier).
// =====================================================================
__global__ __launch_bounds__(NTHR, 1)
void lstm_persist(const float* __restrict__ pre_enc, const float* __restrict__ pre_dec,
                  const float* __restrict__ enc_Wh, const float* __restrict__ dec_Wh,
                  const int* __restrict__ len_enc, const int* __restrict__ len_dec,
                  float* __restrict__ hbuf, float* __restrict__ hs,
                  unsigned* __restrict__ scnt)
{
    extern __shared__ float smf[];
    float* whs  = smf;                    // 16*516
    float* hsm  = smf + 16 * 516;         // 32*516
    float* zbuf = hsm + 32 * 516;         // 2 * 544

    const int tid = threadIdx.x;
    const int cta = blockIdx.x;
    const int wid = tid >> 5;
    const int lane = tid & 31;

    // dot decomposition
    const int wk = wid >> 2;
    const int wq = wid & 3;
    const int base_b = (wq & 1) * 16;
    const int base_z = (wq >> 1) * 8;
    const int lb = lane & 7;
    const int lz = lane >> 3;
    const int rb0 = base_b + lb,     rb1 = base_b + 8 + lb;
    const int rz0 = base_z + lz,     rz1 = base_z + 4 + lz;
    const int kof = wk * 256;

    // gate-phase constants (tid < 128)
    const int gb  = tid >> 2;
    const int ghc = tid & 3;
    const int gn  = cta * 4 + ghc;

    float c_reg = 0.f;
    float pzi = 0.f, pzj = 0.f, pzf = 0.f, pzo = 0.f;

    for (int phase = 0; phase < 2; phase++) {
        const float* Wh  = phase ? dec_Wh  : enc_Wh;
        const float* pre = phase ? pre_dec : pre_enc;
        const int*   len = phase ? len_dec : len_enc;

        for (int i = tid; i < 16 * 512; i += NTHR) {
            int z = i >> 9, k = i & 511;
            whs[z * 516 + k] =
                __ldg(&Wh[(size_t)k * G4 + (z >> 2) * 512 + cta * 4 + (z & 3)]);
        }
        const int mylen = (tid < 128) ? len[gb] : 0;

        // prefetch pz for s = 0
        if (tid < 128) {
            const float* pz = pre + (size_t)gb * G4 + gn;
            pzi = __ldg(pz);
            pzj = __ldg(pz + 512);
            pzf = __ldg(pz + 1024);
            pzo = __ldg(pz + 1536);
        }
        __syncthreads();

        for (int s = 0; s < 64; s++) {
            const int sigma = phase * 64 + s;
            const float* hin  = hbuf + (sigma & 1) * (BSZ * HH);
            float*       hout = hbuf + ((sigma + 1) & 1) * (BSZ * HH);

            // Stage h into smem (uniform; fully unrolled for max MLP).
#pragma unroll
            for (int q = 0; q < 16; q++) {
                const int i = tid + q * NTHR;
                const int b = i >> 7, k4 = i & 127;
                float4 v = __ldcg((const float4*)&hin[b * HH + k4 * 4]);
                *(float4*)&hsm[b * 516 + k4 * 4] = v;
            }
            __syncthreads();

            // 2b x 2zc register tile over this warp's k-half.
            {
                const float* A0 = &hsm[rb0 * 516 + kof];
                const float* A1 = &hsm[rb1 * 516 + kof];
                const float* W0 = &whs[rz0 * 516 + kof];
                const float* W1 = &whs[rz1 * 516 + kof];
                uint64_t a00 = 0, a01 = 0, a10 = 0, a11 = 0;
#pragma unroll 4
                for (int k = 0; k < 256; k += 4) {
                    const ulonglong2 va0 = *(const ulonglong2*)(A0 + k);
                    const ulonglong2 va1 = *(const ulonglong2*)(A1 + k);
                    const ulonglong2 vw0 = *(const ulonglong2*)(W0 + k);
                    const ulonglong2 vw1 = *(const ulonglong2*)(W1 + k);
                    fma2(a00, va0.x, vw0.x); fma2(a00, va0.y, vw0.y);
                    fma2(a01, va0.x, vw1.x); fma2(a01, va0.y, vw1.y);
                    fma2(a10, va1.x, vw0.x); fma2(a10, va1.y, vw0.y);
                    fma2(a11, va1.x, vw1.x); fma2(a11, va1.y, vw1.y);
                }
                float* zb = zbuf + wk * 544;
                zb[rb0 * 17 + rz0] = pairsum(a00);
                zb[rb0 * 17 + rz1] = pairsum(a01);
                zb[rb1 * 17 + rz0] = pairsum(a10);
                zb[rb1 * 17 + rz1] = pairsum(a11);
            }
            __syncthreads();

            if (tid < 128) {
                const int zi0 = gb * 17 + ghc;
                float zi = pzi + zbuf[zi0]      + zbuf[544 + zi0];
                float zj = pzj + zbuf[zi0 + 4]  + zbuf[544 + zi0 + 4];
                float zf = pzf + zbuf[zi0 + 8]  + zbuf[544 + zi0 + 8];
                float zo = pzo + zbuf[zi0 + 12] + zbuf[544 + zi0 + 12];

                float fg = 1.f / (1.f + expf(-(zf + 1.0f)));   // forget bias 1.0
                float ig = 1.f / (1.f + expf(-zi));
                float og = 1.f / (1.f + expf(-zo));
                float cn = c_reg * fg + ig * tanhf(zj);
                float hn = tanhf(cn) * og;

                bool m = (s < mylen);
                float hprev = hsm[gb * 516 + gn];
                c_reg = m ? cn : c_reg;
                hout[gb * HH + gn] = m ? hn : hprev;
                if (phase)
                    hs[((size_t)gb * TY + s) * HH + gn] = m ? hn : 0.f;
            }
            __syncthreads();   // all h stores issued before arrival

            // prefetch pz for step s+1 (off the post-barrier critical path)
            if (tid < 128 && s + 1 < 64) {
                const float* pz = pre + (size_t)(s + 1) * BSZ * G4 + (size_t)gb * G4 + gn;
                pzi = __ldg(pz);
                pzj = __ldg(pz + 512);
                pzf = __ldg(pz + 1024);
                pzo = __ldg(pz + 1536);
            }

            if (tid == 0) {
                unsigned* ctr = scnt + sigma;
                asm volatile("red.release.gpu.global.add.u32 [%0], 1;"
                             :: "l"(ctr) : "memory");
                unsigned v;
                do {
                    asm volatile("ld.relaxed.gpu.global.u32 %0, [%1];"
                                 : "=r"(v) : "l"(ctr) : "memory");
                } while (v < NCTA);
                asm volatile("ld.acquire.gpu.global.u32 %0, [%1];"
                             : "=r"(v) : "l"(ctr) : "memory");
            }
            __syncthreads();   // propagate tid0's acquire to the CTA
        }
    }
}

// =====================================================================
// Host launcher (graph-capturable). lstm_persist stays the 4th kernel.
// =====================================================================
extern "C" void kernel_launch(void* const* d_in, const int* in_sizes, int n_in,
                              void* d_out, int out_size)
{
    const int*   enc_ids = (const int*)d_in[0];
    const int*   dec_ids = (const int*)d_in[1];
    const int*   len_enc = (const int*)d_in[2];
    const int*   len_dec = (const int*)d_in[3];
    const float* E       = (const float*)d_in[4];
    const float* enc_W   = (const float*)d_in[5];
    const float* enc_b   = (const float*)d_in[6];
    const float* dec_W   = (const float*)d_in[7];
    const float* dec_b   = (const float*)d_in[8];
    const float* proj_W  = (const float*)d_in[9];
    float*       out     = (float*)d_out;

    float *pre_enc, *pre_dec, *hbuf, *hs;
    unsigned* scnt;
    int *map, *nvalid;
    cudaGetSymbolAddress((void**)&pre_enc, g_pre_enc);
    cudaGetSymbolAddress((void**)&pre_dec, g_pre_dec);
    cudaGetSymbolAddress((void**)&hbuf,    g_hbuf);
    cudaGetSymbolAddress((void**)&hs,      g_hs);
    cudaGetSymbolAddress((void**)&scnt,    g_scnt);
    cudaGetSymbolAddress((void**)&map,     g_map);
    cudaGetSymbolAddress((void**)&nvalid,  g_nvalid);

    __nv_bfloat16 *WeT_hi, *WeT_lo, *WdT_hi, *WdT_lo;
    __nv_bfloat16 *Ae_hi, *Ae_lo, *Ad_hi, *Ad_lo;
    __half *Bt_h, *Ah_h;
    cudaGetSymbolAddress((void**)&WeT_hi, g_WeT_hi);
    cudaGetSymbolAddress((void**)&WeT_lo, g_WeT_lo);
    cudaGetSymbolAddress((void**)&WdT_hi, g_WdT_hi);
    cudaGetSymbolAddress((void**)&WdT_lo, g_WdT_lo);
    cudaGetSymbolAddress((void**)&Ae_hi,  g_Ae_hi);
    cudaGetSymbolAddress((void**)&Ae_lo,  g_Ae_lo);
    cudaGetSymbolAddress((void**)&Ad_hi,  g_Ad_hi);
    cudaGetSymbolAddress((void**)&Ad_lo,  g_Ad_lo);
    cudaGetSymbolAddress((void**)&Bt_h,   g_Bt_h);
    cudaGetSymbolAddress((void**)&Ah_h,   g_Ah_h);

    const size_t lstm_smem  = (16 * 516 + 32 * 516 + 2 * 544) * sizeof(float);
    const size_t gemm_smem  = 3 * 4 * 16384;   // 192KB (bf16 3-term preact)
    const size_t gemm1_smem = 3 * 2 * 16384;   // 96KB (fp16 1-term proj)
    static bool attr_set = false;
    if (!attr_set) {
        cudaFuncSetAttribute(lstm_persist,
                             cudaFuncAttributeMaxDynamicSharedMemorySize, (int)lstm_smem);
        cudaFuncSetAttribute(mma_gemm_pre,
                             cudaFuncAttributeMaxDynamicSharedMemorySize, (int)gemm_smem);
        cudaFuncSetAttribute(mma_gemm_h1,
                             cudaFuncAttributeMaxDynamicSharedMemorySize, (int)gemm1_smem);
        attr_set = true;
    }

    // (1) zero h + step counters; build compact map (block 0)
    zero_init<<<64, 256>>>(hbuf, scnt, len_dec, map, nvalid);

    // (2) fused Wx transposes + embedding gathers
    prep<<<dim3(4096, 1, 4), 256>>>(enc_W, dec_W, WeT_hi, WeT_lo, WdT_hi, WdT_lo,
                                    E, enc_ids, dec_ids,
                                    Ae_hi, Ae_lo, Ad_hi, Ad_lo);

    // (3) fused pre-activation GEMMs (enc & dec)
    mma_gemm_pre<<<dim3(16, G4 / 128, 2), 256, gemm_smem>>>(
        Ae_hi, Ae_lo, WeT_hi, WeT_lo, enc_b, pre_enc,
        Ad_hi, Ad_lo, WdT_hi, WdT_lo, dec_b, pre_dec);

    // (4) full recurrence — profiled launch
    lstm_persist<<<NCTA, NTHR, lstm_smem>>>(
        pre_enc, pre_dec,
        enc_W + (size_t)DD * G4, dec_W + (size_t)DD * G4,
        len_enc, len_dec, hbuf, hs, scnt);

    // (5..) zero invalid output rows, then the projection chain
    zero_invalid<<<dim3(32, BSZ * TY), 256>>>(len_dec, out);
    transpose_f16<<<dim3(VV / 32, DD / 32), 256>>>(proj_W, VV, Bt_h);
    compact_f16<<<(BSZ * TY * DD) / 256, 256>>>(hs, map, Ah_h);
    mma_gemm_h1<<<dim3(16, VV / 128), 256, gemm1_smem>>>(Ah_h, Bt_h,
                                                         out, VV, map, nvalid);
}

// round 16
// speedup vs baseline: 1.1845x; 1.0340x over previous
#include <cuda_runtime.h>
#include <cuda_bf16.h>
#include <cuda_fp16.h>
#include <math.h>
#include <stdint.h>

// Problem constants
#define BSZ 32
#define TX  64
#define TY  64
#define DD  512
#define HH  512
#define G4  2048   // 4*H
#define VV  32000

#define NCTA 128   // persistent LSTM CTAs
#define NTHR 256

// ---------------- scratch (device globals; no allocation allowed) ----------------
__device__ float g_pre_enc[TX * BSZ * G4];
__device__ float g_pre_dec[TY * BSZ * G4];
__device__ float g_hbuf[2][BSZ * HH];
__device__ float g_hs[BSZ * TY * HH];
__device__ unsigned g_scnt[TX + TY];   // per-step arrival counters
__device__ int g_map[BSZ * TY];        // projection: compact row -> b*64+t, -1 = pad
__device__ int g_mapE[BSZ * TX];       // enc preact: compact row -> t*32+b, -1 = pad
__device__ int g_mapD[BSZ * TY];       // dec preact: compact row -> t*32+b, -1 = pad
__device__ int g_nvalid[3];            // [0]=proj/dec rows, [1]=enc rows, [2]=dec rows

// bf16 3-term operands for the pre-activation GEMMs (K-major, K=512)
__device__ __nv_bfloat16 g_WeT_hi[G4 * DD], g_WeT_lo[G4 * DD];
__device__ __nv_bfloat16 g_WdT_hi[G4 * DD], g_WdT_lo[G4 * DD];
__device__ __nv_bfloat16 g_Ae_hi[TX * BSZ * DD], g_Ae_lo[TX * BSZ * DD];   // compact rows
__device__ __nv_bfloat16 g_Ad_hi[TY * BSZ * DD], g_Ad_lo[TY * BSZ * DD];   // compact rows

// fp16 1-term operands for the projection GEMM
__device__ __half g_Bt_h[VV * DD];
__device__ __half g_Ah_h[BSZ * TY * DD];

// ======================= helpers =======================
__device__ __forceinline__ uint32_t smem_u32(const void* p) {
    uint32_t a;
    asm("{ .reg .u64 t; cvta.to.shared.u64 t, %1; cvt.u32.u64 %0, t; }" : "=r"(a) : "l"(p));
    return a;
}

#define LDSM4(r, addr) \
    asm volatile("ldmatrix.sync.aligned.m8n8.x4.shared.b16 {%0,%1,%2,%3}, [%4];" \
        : "=r"((r)[0]), "=r"((r)[1]), "=r"((r)[2]), "=r"((r)[3]) : "r"(addr))

#define MMA_BF16(d, a, b0, b1) \
    asm volatile("mma.sync.aligned.m16n8k16.row.col.f32.bf16.bf16.f32 " \
        "{%0,%1,%2,%3}, {%4,%5,%6,%7}, {%8,%9}, {%0,%1,%2,%3};" \
        : "+f"((d)[0]), "+f"((d)[1]), "+f"((d)[2]), "+f"((d)[3]) \
        : "r"((a)[0]), "r"((a)[1]), "r"((a)[2]), "r"((a)[3]), "r"(b0), "r"(b1))

#define MMA_F16(d, a, b0, b1) \
    asm volatile("mma.sync.aligned.m16n8k16.row.col.f32.f16.f16.f32 " \
        "{%0,%1,%2,%3}, {%4,%5,%6,%7}, {%8,%9}, {%0,%1,%2,%3};" \
        : "+f"((d)[0]), "+f"((d)[1]), "+f"((d)[2]), "+f"((d)[3]) \
        : "r"((a)[0]), "r"((a)[1]), "r"((a)[2]), "r"((a)[3]), "r"(b0), "r"(b1))

#define CP_ASYNC16(dst, src) \
    asm volatile("cp.async.cg.shared.global [%0], [%1], 16;" :: "r"(dst), "l"(src))
#define CP_COMMIT()  asm volatile("cp.async.commit_group;" ::: "memory")
#define CP_WAIT(n)   asm volatile("cp.async.wait_group %0;" :: "n"(n) : "memory")

// packed f32x2 FMA (Blackwell base ISA)
__device__ __forceinline__ void fma2(uint64_t& d, uint64_t a, uint64_t b) {
    asm("fma.rn.f32x2 %0, %1, %2, %0;" : "+l"(d) : "l"(a), "l"(b));
}
__device__ __forceinline__ float pairsum(uint64_t v) {
    return __uint_as_float((uint32_t)v) + __uint_as_float((uint32_t)(v >> 32));
}

// =====================================================================
// Fused init: zero h state + step counters; block 0 builds all three
// compact maps (projection b*64+t ordering; preacts t*32+b row ids).
// =====================================================================
__global__ void zero_init(float* __restrict__ hbuf, unsigned* __restrict__ scnt,
                          const int* __restrict__ len_enc, const int* __restrict__ len_dec,
                          int* __restrict__ map, int* __restrict__ mapE,
                          int* __restrict__ mapD, int* __restrict__ nvalid)
{
    const int i = blockIdx.x * 256 + threadIdx.x;
    if (i < BSZ * HH) hbuf[i] = 0.f;
    if (i < TX + TY)  scnt[i] = 0u;

    if (blockIdx.x == 0) {
        __shared__ int offP[BSZ], offE[BSZ], offD[BSZ];
        const int tid = threadIdx.x;
        if (tid == 0) {
            int aP = 0, aE = 0, aD = 0;
            for (int b = 0; b < BSZ; b++) {
                int Ld = len_dec[b]; if (Ld < 0) Ld = 0; if (Ld > TY) Ld = TY;
                int Le = len_enc[b]; if (Le < 0) Le = 0; if (Le > TX) Le = TX;
                offP[b] = aP; aP += Ld;
                offE[b] = aE; aE += Le;
                offD[b] = aD; aD += Ld;
            }
            nvalid[0] = aP;
            nvalid[1] = aE;
            nvalid[2] = aD;
        }
        __syncthreads();
        for (int j = tid; j < BSZ * TY; j += 256) { map[j] = -1; mapD[j] = -1; }
        for (int j = tid; j < BSZ * TX; j += 256) mapE[j] = -1;
        __syncthreads();
        for (int b = 0; b < BSZ; b++) {
            int Ld = len_dec[b]; if (Ld > TY) Ld = TY;
            int Le = len_enc[b]; if (Le > TX) Le = TX;
            for (int t = tid; t < Ld; t += 256) {
                map[offP[b] + t]  = b * TY + t;      // projection (hs row id)
                mapD[offD[b] + t] = t * BSZ + b;     // dec preact (pre row id)
            }
            for (int t = tid; t < Le; t += 256)
                mapE[offE[b] + t] = t * BSZ + b;     // enc preact (pre row id)
        }
    }
}

// =====================================================================
// Fused prep: z=0,1 -> Wx transpose+split (enc/dec); z=2,3 -> embedding
// gather+split into COMPACT rows via mapE/mapD (pad rows zeroed).
// =====================================================================
__global__ void prep(const float* __restrict__ enc_W, const float* __restrict__ dec_W,
                     __nv_bfloat16* __restrict__ WeT_hi, __nv_bfloat16* __restrict__ WeT_lo,
                     __nv_bfloat16* __restrict__ WdT_hi, __nv_bfloat16* __restrict__ WdT_lo,
                     const float* __restrict__ E,
                     const int* __restrict__ idsE, const int* __restrict__ idsD,
                     const int* __restrict__ mapE, const int* __restrict__ mapD,
                     __nv_bfloat16* __restrict__ Ae_hi, __nv_bfloat16* __restrict__ Ae_lo,
                     __nv_bfloat16* __restrict__ Ad_hi, __nv_bfloat16* __restrict__ Ad_lo)
{
    const int z = blockIdx.z;
    if (z < 2) {
        if (blockIdx.x >= (G4 / 32) * (DD / 32)) return;   // 64*16 = 1024 tiles
        const float* src = z ? dec_W : enc_W;
        __nv_bfloat16* hi = z ? WdT_hi : WeT_hi;
        __nv_bfloat16* lo = z ? WdT_lo : WeT_lo;

        __shared__ float t[32][33];
        const int tx = threadIdx.x & 31, ty = threadIdx.x >> 5;
        const int bx = blockIdx.x & 63, by = blockIdx.x >> 6;
        const int n = bx * 32 + tx;
        const int kb = by * 32;
#pragma unroll
        for (int r = 0; r < 32; r += 8)
            t[ty + r][tx] = src[(size_t)(kb + ty + r) * G4 + n];
        __syncthreads();
#pragma unroll
        for (int r = 0; r < 32; r += 8) {
            const int nn = bx * 32 + ty + r;
            const int kk = kb + tx;
            const float v = t[tx][ty + r];
            const __nv_bfloat16 h = __float2bfloat16(v);
            hi[(size_t)nn * DD + kk] = h;
            lo[(size_t)nn * DD + kk] = __float2bfloat16(v - __bfloat162float(h));
        }
    } else {
        const int* ids = (z == 3) ? idsD : idsE;
        const int* mp  = (z == 3) ? mapD : mapE;
        __nv_bfloat16* hi = (z == 3) ? Ad_hi : Ae_hi;
        __nv_bfloat16* lo = (z == 3) ? Ad_lo : Ae_lo;
        const int idxT = (z == 3) ? TY : TX;

        const int i = blockIdx.x * 256 + threadIdx.x;
        const int j = i >> 9, k = i & 511;
        const int m = mp[j];                   // original row t*32+b, or -1
        float v = 0.f;
        if (m >= 0) {
            const int b = m & 31, t = m >> 5;
            v = E[(size_t)ids[b * idxT + t] * DD + k];
        }
        const __nv_bfloat16 h = __float2bfloat16(v);
        hi[i] = h;
        lo[i] = __float2bfloat16(v - __bfloat162float(h));
    }
}

// =====================================================================
// Fused 3-term split-bf16 GEMM for BOTH pre-activations (z = 0 enc, 1 dec),
// M-compacted: CTAs past nvalid exit; C rows scatter through the map.
// =====================================================================
__global__ __launch_bounds__(256, 1)
void mma_gemm_pre(const __nv_bfloat16* __restrict__ AhiE, const __nv_bfloat16* __restrict__ AloE,
                  const __nv_bfloat16* __restrict__ BhiE, const __nv_bfloat16* __restrict__ BloE,
                  const float* __restrict__ biasE, float* __restrict__ CE,
                  const __nv_bfloat16* __restrict__ AhiD, const __nv_bfloat16* __restrict__ AloD,
                  const __nv_bfloat16* __restrict__ BhiD, const __nv_bfloat16* __restrict__ BloD,
                  const float* __restrict__ biasD, float* __restrict__ CD,
                  const int* __restrict__ mapE, const int* __restrict__ mapD,
                  const int* __restrict__ nvalid)
{
    const int m0 = blockIdx.x * 128;
    if (m0 >= nvalid[1 + blockIdx.z]) return;

    const __nv_bfloat16* Ahi = blockIdx.z ? AhiD : AhiE;
    const __nv_bfloat16* Alo = blockIdx.z ? AloD : AloE;
    const __nv_bfloat16* Bhi = blockIdx.z ? BhiD : BhiE;
    const __nv_bfloat16* Blo = blockIdx.z ? BloD : BloE;
    const float* bias = blockIdx.z ? biasD : biasE;
    float* C = blockIdx.z ? CD : CE;
    const int* mp = blockIdx.z ? mapD : mapE;
    const int N = G4;

    extern __shared__ char smc[];
    const uint32_t sbase = smem_u32(smc);

    const int tid  = threadIdx.x;
    const int wid  = tid >> 5;
    const int lane = tid & 31;
    const int n0 = blockIdx.y * 128;
    const int wm = (wid & 3) * 32;
    const int wn = (wid >> 2) * 64;

    const __nv_bfloat16* srcs[4] = { Ahi, Alo, Bhi, Blo };
    const int rb[4] = { m0, m0, n0, n0 };

    uint32_t dsts[4];
    const __nv_bfloat16* gsrc[4][4];
#pragma unroll
    for (int q = 0; q < 4; q++) {
        const int i = tid + q * 256;
        const int r = i >> 3, u = i & 7;
        dsts[q] = (uint32_t)(r * 128 + ((u ^ (r & 7)) << 4));
#pragma unroll
        for (int t4 = 0; t4 < 4; t4++)
            gsrc[t4][q] = srcs[t4] + (size_t)(rb[t4] + r) * DD + u * 8;
    }

    float acc[2][8][4];
#pragma unroll
    for (int mt = 0; mt < 2; mt++)
#pragma unroll
        for (int nt = 0; nt < 8; nt++)
#pragma unroll
            for (int e = 0; e < 4; e++) acc[mt][nt][e] = 0.f;

#pragma unroll
    for (int s = 0; s < 2; s++) {
        const uint32_t sb = sbase + (uint32_t)s * 65536u;
        const int koff = s * 64;
#pragma unroll
        for (int t4 = 0; t4 < 4; t4++)
#pragma unroll
            for (int q = 0; q < 4; q++)
                CP_ASYNC16(sb + t4 * 16384 + dsts[q], gsrc[t4][q] + koff);
        CP_COMMIT();
    }

    const int lrow15 = lane & 15;
    const int lhalf  = lane >> 4;

    int cs = 0;
    for (int it = 0; it < 8; it++) {
        if (it < 7) { CP_WAIT(1); } else { CP_WAIT(0); }
        __syncthreads();

        if (it + 2 < 8) {
            int ps = cs + 2; if (ps >= 3) ps -= 3;
            const uint32_t sb = sbase + (uint32_t)ps * 65536u;
            const int koff = (it + 2) * 64;
#pragma unroll
            for (int t4 = 0; t4 < 4; t4++)
#pragma unroll
                for (int q = 0; q < 4; q++)
                    CP_ASYNC16(sb + t4 * 16384 + dsts[q], gsrc[t4][q] + koff);
            CP_COMMIT();
        }

        const uint32_t B = sbase + (uint32_t)cs * 65536u;

#pragma unroll
        for (int j = 0; j < 4; j++) {
            uint32_t ah[2][4], al[2][4];
            uint32_t bh[4][4], bl[4][4];
#pragma unroll
            for (int mt = 0; mt < 2; mt++) {
                const int row = wm + mt * 16 + lrow15;
                const int unit = j * 2 + lhalf;
                const uint32_t addr = B + row * 128 + (((unit ^ (row & 7))) << 4);
                LDSM4(ah[mt], addr);
                LDSM4(al[mt], addr + 16384);
            }
#pragma unroll
            for (int g = 0; g < 4; g++) {
                const int row = wn + g * 16 + lrow15;
                const int unit = j * 2 + lhalf;
                const uint32_t addr = B + 32768 + row * 128 + (((unit ^ (row & 7))) << 4);
                LDSM4(bh[g], addr);
                LDSM4(bl[g], addr + 16384);
            }
#pragma unroll
            for (int mt = 0; mt < 2; mt++)
#pragma unroll
                for (int nt = 0; nt < 8; nt++) {
                    const int g = nt >> 1, o = nt & 1;
                    MMA_BF16(acc[mt][nt], ah[mt], bh[g][o], bh[g][o + 2]);
                    MMA_BF16(acc[mt][nt], ah[mt], bl[g][o], bl[g][o + 2]);
                    MMA_BF16(acc[mt][nt], al[mt], bh[g][o], bh[g][o + 2]);
                }
        }
        cs++; if (cs == 3) cs = 0;
    }

    const int erow = wm + (lane >> 2);
    const int ec = n0 + wn + (lane & 3) * 2;
#pragma unroll
    for (int mt = 0; mt < 2; mt++) {
        const int r0 = m0 + erow + mt * 16;
        const int r1 = r0 + 8;
        const int o0 = mp[r0];
        const int o1 = mp[r1];
#pragma unroll
        for (int nt = 0; nt < 8; nt++) {
            const int col = ec + nt * 8;
            const float b0 = bias[col], b1 = bias[col + 1];
            if (o0 >= 0) {
                float* p0 = C + (size_t)o0 * N + col;
                p0[0] = acc[mt][nt][0] + b0;
                p0[1] = acc[mt][nt][1] + b1;
            }
            if (o1 >= 0) {
                float* p1 = C + (size_t)o1 * N + col;
                p1[0] = acc[mt][nt][2] + b0;
                p1[1] = acc[mt][nt][3] + b1;
            }
        }
    }
}

// =====================================================================
// 1-term fp16 GEMM (projection): C = fp16(A) @ fp16(B)^T, compacted.
// =====================================================================
__global__ __launch_bounds__(256, 1)
void mma_gemm_h1(const __half* __restrict__ Ah, const __half* __restrict__ Bh,
                 float* __restrict__ C, int N,
                 const int* __restrict__ map, const int* __restrict__ nvalidp)
{
    const int m0 = blockIdx.x * 128;
    const int n0 = blockIdx.y * 128;
    if (m0 >= *nvalidp) return;

    extern __shared__ char smc[];
    const uint32_t sbase = smem_u32(smc);

    const int tid  = threadIdx.x;
    const int wid  = tid >> 5;
    const int lane = tid & 31;
    const int wm = (wid & 3) * 32;
    const int wn = (wid >> 2) * 64;

    const __half* srcs[2] = { Ah, Bh };
    const int rb[2] = { m0, n0 };

    uint32_t dsts[4];
    const __half* gsrc[2][4];
#pragma unroll
    for (int q = 0; q < 4; q++) {
        const int i = tid + q * 256;
        const int r = i >> 3, u = i & 7;
        dsts[q] = (uint32_t)(r * 128 + ((u ^ (r & 7)) << 4));
#pragma unroll
        for (int t2 = 0; t2 < 2; t2++)
            gsrc[t2][q] = srcs[t2] + (size_t)(rb[t2] + r) * DD + u * 8;
    }

    float acc[2][8][4];
#pragma unroll
    for (int mt = 0; mt < 2; mt++)
#pragma unroll
        for (int nt = 0; nt < 8; nt++)
#pragma unroll
            for (int e = 0; e < 4; e++) acc[mt][nt][e] = 0.f;

#pragma unroll
    for (int s = 0; s < 2; s++) {
        const uint32_t sb = sbase + (uint32_t)s * 32768u;
        const int koff = s * 64;
#pragma unroll
        for (int t2 = 0; t2 < 2; t2++)
#pragma unroll
            for (int q = 0; q < 4; q++)
                CP_ASYNC16(sb + t2 * 16384 + dsts[q], gsrc[t2][q] + koff);
        CP_COMMIT();
    }

    const int lrow15 = lane & 15;
    const int lhalf  = lane >> 4;

    int cs = 0;
    for (int it = 0; it < 8; it++) {
        if (it < 7) { CP_WAIT(1); } else { CP_WAIT(0); }
        __syncthreads();

        if (it + 2 < 8) {
            int ps = cs + 2; if (ps >= 3) ps -= 3;
            const uint32_t sb = sbase + (uint32_t)ps * 32768u;
            const int koff = (it + 2) * 64;
#pragma unroll
            for (int t2 = 0; t2 < 2; t2++)
#pragma unroll
                for (int q = 0; q < 4; q++)
                    CP_ASYNC16(sb + t2 * 16384 + dsts[q], gsrc[t2][q] + koff);
            CP_COMMIT();
        }

        const uint32_t B = sbase + (uint32_t)cs * 32768u;

#pragma unroll
        for (int j = 0; j < 4; j++) {
            uint32_t ah[2][4];
            uint32_t bh[4][4];
#pragma unroll
            for (int mt = 0; mt < 2; mt++) {
                const int row = wm + mt * 16 + lrow15;
                const int unit = j * 2 + lhalf;
                LDSM4(ah[mt], B + row * 128 + (((unit ^ (row & 7))) << 4));
            }
#pragma unroll
            for (int g = 0; g < 4; g++) {
                const int row = wn + g * 16 + lrow15;
                const int unit = j * 2 + lhalf;
                LDSM4(bh[g], B + 16384 + row * 128 + (((unit ^ (row & 7))) << 4));
            }
#pragma unroll
            for (int mt = 0; mt < 2; mt++)
#pragma unroll
                for (int nt = 0; nt < 8; nt++) {
                    const int g = nt >> 1, o = nt & 1;
                    MMA_F16(acc[mt][nt], ah[mt], bh[g][o], bh[g][o + 2]);
                }
        }
        cs++; if (cs == 3) cs = 0;
    }

    const int erow = wm + (lane >> 2);
    const int ec = n0 + wn + (lane & 3) * 2;
#pragma unroll
    for (int mt = 0; mt < 2; mt++) {
        const int r0 = m0 + erow + mt * 16;
        const int r1 = r0 + 8;
        const int o0 = map[r0];
        const int o1 = map[r1];
#pragma unroll
        for (int nt = 0; nt < 8; nt++) {
            const int col = ec + nt * 8;
            if (o0 >= 0) {
                float* p0 = C + (size_t)o0 * N + col;
                p0[0] = acc[mt][nt][0];
                p0[1] = acc[mt][nt][1];
            }
            if (o1 >= 0) {
                float* p1 = C + (size_t)o1 * N + col;
                p1[0] = acc[mt][nt][2];
                p1[1] = acc[mt][nt][3];
            }
        }
    }
}

// Zero only the invalid output rows (t >= len_dec[b]).
__global__ void zero_invalid(const int* __restrict__ len_dec, float* __restrict__ out)
{
    const int row = blockIdx.y;          // b*64 + t
    const int b = row >> 6, t = row & 63;
    if (t < len_dec[b]) return;
    const int i = blockIdx.x * 1024 + threadIdx.x * 4;
    if (i < VV) {
        float4 z = make_float4(0.f, 0.f, 0.f, 0.f);
        *(float4*)(out + (size_t)row * VV + i) = z;
    }
}

// Compact hs into fp16 (single term).
__global__ void compact_f16(const float* __restrict__ src,
                            const int* __restrict__ map,
                            __half* __restrict__ dst)
{
    const int i = blockIdx.x * 256 + threadIdx.x;
    const int j = i >> 9, k = i & 511;
    const int s = map[j];
    const float v = (s >= 0) ? src[(size_t)s * DD + k] : 0.f;
    dst[i] = __float2half(v);
}

// Transpose + fp16:  src[K=512][VV] f32  ->  h [VV][512] fp16
__global__ void transpose_f16(const float* __restrict__ src, int N,
                              __half* __restrict__ dst)
{
    __shared__ float t[32][33];
    const int tx = threadIdx.x & 31, ty = threadIdx.x >> 5;
    const int n = blockIdx.x * 32 + tx;
    const int kb = blockIdx.y * 32;
#pragma unroll
    for (int r = 0; r < 32; r += 8)
        t[ty + r][tx] = src[(size_t)(kb + ty + r) * N + n];
    __syncthreads();
#pragma unroll
    for (int r = 0; r < 32; r += 8) {
        const int nn = blockIdx.x * 32 + ty + r;
        const int kk = kb + tx;
        dst[(size_t)nn * DD + kk] = __float2half(t[tx][ty + r]);
    }
}

// =====================================================================
// Persistent LSTM — PROVEN R13 version verbatim.
// (Invalid pre rows now hold stale data; all reads of them feed only
//  mask-discarded values, so results are bit-identical.)
// =====================================================================
__global__ __launch_bounds__(NTHR, 1)
void lstm_persist(const float* __restrict__ pre_enc, const float* __restrict__ pre_dec,
                  const float* __restrict__ enc_Wh, const float* __restrict__ dec_Wh,
                  const int* __restrict__ len_enc, const int* __restrict__ len_dec,
                  float* __restrict__ hbuf, float* __restrict__ hs,
                  unsigned* __restrict__ scnt)
{
    extern __shared__ float smf[];
    float* whs  = smf;                    // 16*516
    float* hsm  = smf + 16 * 516;         // 32*516
    float* zbuf = hsm + 32 * 516;         // 2 * 544

    const int tid = threadIdx.x;
    const int cta = blockIdx.x;
    const int wid = tid >> 5;
    const int lane = tid & 31;

    // dot decomposition
    const int wk = wid >> 2;
    const int wq = wid & 3;
    const int base_b = (wq & 1) * 16;
    const int base_z = (wq >> 1) * 8;
    const int lb = lane & 7;
    const int lz = lane >> 3;
    const int rb0 = base_b + lb,     rb1 = base_b + 8 + lb;
    const int rz0 = base_z + lz,     rz1 = base_z + 4 + lz;
    const int kof = wk * 256;

    // gate-phase constants (tid < 128)
    const int gb  = tid >> 2;
    const int ghc = tid & 3;
    const int gn  = cta * 4 + ghc;

    float c_reg = 0.f;
    float pzi = 0.f, pzj = 0.f, pzf = 0.f, pzo = 0.f;

    for (int phase = 0; phase < 2; phase++) {
        const float* Wh  = phase ? dec_Wh  : enc_Wh;
        const float* pre = phase ? pre_dec : pre_enc;
        const int*   len = phase ? len_dec : len_enc;

        for (int i = tid; i < 16 * 512; i += NTHR) {
            int z = i >> 9, k = i & 511;
            whs[z * 516 + k] =
                __ldg(&Wh[(size_t)k * G4 + (z >> 2) * 512 + cta * 4 + (z & 3)]);
        }
        const int mylen = (tid < 128) ? len[gb] : 0;

        // prefetch pz for s = 0
        if (tid < 128) {
            const float* pz = pre + (size_t)gb * G4 + gn;
            pzi = __ldg(pz);
            pzj = __ldg(pz + 512);
            pzf = __ldg(pz + 1024);
            pzo = __ldg(pz + 1536);
        }
        __syncthreads();

        for (int s = 0; s < 64; s++) {
            const int sigma = phase * 64 + s;
            const float* hin  = hbuf + (sigma & 1) * (BSZ * HH);
            float*       hout = hbuf + ((sigma + 1) & 1) * (BSZ * HH);

            // Stage h into smem (uniform; fully unrolled for max MLP).
#pragma unroll
            for (int q = 0; q < 16; q++) {
                const int i = tid + q * NTHR;
                const int b = i >> 7, k4 = i & 127;
                float4 v = __ldcg((const float4*)&hin[b * HH + k4 * 4]);
                *(float4*)&hsm[b * 516 + k4 * 4] = v;
            }
            __syncthreads();

            // 2b x 2zc register tile over this warp's k-half.
            {
                const float* A0 = &hsm[rb0 * 516 + kof];
                const float* A1 = &hsm[rb1 * 516 + kof];
                const float* W0 = &whs[rz0 * 516 + kof];
                const float* W1 = &whs[rz1 * 516 + kof];
                uint64_t a00 = 0, a01 = 0, a10 = 0, a11 = 0;
#pragma unroll 4
                for (int k = 0; k < 256; k += 4) {
                    const ulonglong2 va0 = *(const ulonglong2*)(A0 + k);
                    const ulonglong2 va1 = *(const ulonglong2*)(A1 + k);
                    const ulonglong2 vw0 = *(const ulonglong2*)(W0 + k);
                    const ulonglong2 vw1 = *(const ulonglong2*)(W1 + k);
                    fma2(a00, va0.x, vw0.x); fma2(a00, va0.y, vw0.y);
                    fma2(a01, va0.x, vw1.x); fma2(a01, va0.y, vw1.y);
                    fma2(a10, va1.x, vw0.x); fma2(a10, va1.y, vw0.y);
                    fma2(a11, va1.x, vw1.x); fma2(a11, va1.y, vw1.y);
                }
                float* zb = zbuf + wk * 544;
                zb[rb0 * 17 + rz0] = pairsum(a00);
                zb[rb0 * 17 + rz1] = pairsum(a01);
                zb[rb1 * 17 + rz0] = pairsum(a10);
                zb[rb1 * 17 + rz1] = pairsum(a11);
            }
            __syncthreads();

            if (tid < 128) {
                const int zi0 = gb * 17 + ghc;
                float zi = pzi + zbuf[zi0]      + zbuf[544 + zi0];
                float zj = pzj + zbuf[zi0 + 4]  + zbuf[544 + zi0 + 4];
                float zf = pzf + zbuf[zi0 + 8]  + zbuf[544 + zi0 + 8];
                float zo = pzo + zbuf[zi0 + 12] + zbuf[544 + zi0 + 12];

                float fg = 1.f / (1.f + expf(-(zf + 1.0f)));   // forget bias 1.0
                float ig = 1.f / (1.f + expf(-zi));
                float og = 1.f / (1.f + expf(-zo));
                float cn = c_reg * fg + ig * tanhf(zj);
                float hn = tanhf(cn) * og;

                bool m = (s < mylen);
                float hprev = hsm[gb * 516 + gn];
                c_reg = m ? cn : c_reg;
                hout[gb * HH + gn] = m ? hn : hprev;
                if (phase)
                    hs[((size_t)gb * TY + s) * HH + gn] = m ? hn : 0.f;
            }
            __syncthreads();   // all h stores issued before arrival

            // prefetch pz for step s+1 (off the post-barrier critical path)
            if (tid < 128 && s + 1 < 64) {
                const float* pz = pre + (size_t)(s + 1) * BSZ * G4 + (size_t)gb * G4 + gn;
                pzi = __ldg(pz);
                pzj = __ldg(pz + 512);
                pzf = __ldg(pz + 1024);
                pzo = __ldg(pz + 1536);
            }

            if (tid == 0) {
                unsigned* ctr = scnt + sigma;
                asm volatile("red.release.gpu.global.add.u32 [%0], 1;"
                             :: "l"(ctr) : "memory");
                unsigned v;
                do {
                    asm volatile("ld.relaxed.gpu.global.u32 %0, [%1];"
                                 : "=r"(v) : "l"(ctr) : "memory");
                } while (v < NCTA);
                asm volatile("ld.acquire.gpu.global.u32 %0, [%1];"
                             : "=r"(v) : "l"(ctr) : "memory");
            }
            __syncthreads();   // propagate tid0's acquire to the CTA
        }
    }
}

// =====================================================================
// Host launcher (graph-capturable). lstm_persist stays the 4th kernel.
// =====================================================================
extern "C" void kernel_launch(void* const* d_in, const int* in_sizes, int n_in,
                              void* d_out, int out_size)
{
    const int*   enc_ids = (const int*)d_in[0];
    const int*   dec_ids = (const int*)d_in[1];
    const int*   len_enc = (const int*)d_in[2];
    const int*   len_dec = (const int*)d_in[3];
    const float* E       = (const float*)d_in[4];
    const float* enc_W   = (const float*)d_in[5];
    const float* enc_b   = (const float*)d_in[6];
    const float* dec_W   = (const float*)d_in[7];
    const float* dec_b   = (const float*)d_in[8];
    const float* proj_W  = (const float*)d_in[9];
    float*       out     = (float*)d_out;

    float *pre_enc, *pre_dec, *hbuf, *hs;
    unsigned* scnt;
    int *map, *mapE, *mapD, *nvalid;
    cudaGetSymbolAddress((void**)&pre_enc, g_pre_enc);
    cudaGetSymbolAddress((void**)&pre_dec, g_pre_dec);
    cudaGetSymbolAddress((void**)&hbuf,    g_hbuf);
    cudaGetSymbolAddress((void**)&hs,      g_hs);
    cudaGetSymbolAddress((void**)&scnt,    g_scnt);
    cudaGetSymbolAddress((void**)&map,     g_map);
    cudaGetSymbolAddress((void**)&mapE,    g_mapE);
    cudaGetSymbolAddress((void**)&mapD,    g_mapD);
    cudaGetSymbolAddress((void**)&nvalid,  g_nvalid);

    __nv_bfloat16 *WeT_hi, *WeT_lo, *WdT_hi, *WdT_lo;
    __nv_bfloat16 *Ae_hi, *Ae_lo, *Ad_hi, *Ad_lo;
    __half *Bt_h, *Ah_h;
    cudaGetSymbolAddress((void**)&WeT_hi, g_WeT_hi);
    cudaGetSymbolAddress((void**)&WeT_lo, g_WeT_lo);
    cudaGetSymbolAddress((void**)&WdT_hi, g_WdT_hi);
    cudaGetSymbolAddress((void**)&WdT_lo, g_WdT_lo);
    cudaGetSymbolAddress((void**)&Ae_hi,  g_Ae_hi);
    cudaGetSymbolAddress((void**)&Ae_lo,  g_Ae_lo);
    cudaGetSymbolAddress((void**)&Ad_hi,  g_Ad_hi);
    cudaGetSymbolAddress((void**)&Ad_lo,  g_Ad_lo);
    cudaGetSymbolAddress((void**)&Bt_h,   g_Bt_h);
    cudaGetSymbolAddress((void**)&Ah_h,   g_Ah_h);

    const size_t lstm_smem  = (16 * 516 + 32 * 516 + 2 * 544) * sizeof(float);
    const size_t gemm_smem  = 3 * 4 * 16384;   // 192KB (bf16 3-term preact)
    const size_t gemm1_smem = 3 * 2 * 16384;   // 96KB (fp16 1-term proj)
    static bool attr_set = false;
    if (!attr_set) {
        cudaFuncSetAttribute(lstm_persist,
                             cudaFuncAttributeMaxDynamicSharedMemorySize, (int)lstm_smem);
        cudaFuncSetAttribute(mma_gemm_pre,
                             cudaFuncAttributeMaxDynamicSharedMemorySize, (int)gemm_smem);
        cudaFuncSetAttribute(mma_gemm_h1,
                             cudaFuncAttributeMaxDynamicSharedMemorySize, (int)gemm1_smem);
        attr_set = true;
    }

    // (1) zero h + step counters; build all three compact maps (block 0)
    zero_init<<<64, 256>>>(hbuf, scnt, len_enc, len_dec, map, mapE, mapD, nvalid);

    // (2) fused Wx transposes + compact embedding gathers
    prep<<<dim3(4096, 1, 4), 256>>>(enc_W, dec_W, WeT_hi, WeT_lo, WdT_hi, WdT_lo,
                                    E, enc_ids, dec_ids, mapE, mapD,
                                    Ae_hi, Ae_lo, Ad_hi, Ad_lo);

    // (3) fused pre-activation GEMMs (enc & dec), M-compacted + scattered
    mma_gemm_pre<<<dim3(16, G4 / 128, 2), 256, gemm_smem>>>(
        Ae_hi, Ae_lo, WeT_hi, WeT_lo, enc_b, pre_enc,
        Ad_hi, Ad_lo, WdT_hi, WdT_lo, dec_b, pre_dec,
        mapE, mapD, nvalid);

    // (4) full recurrence — profiled launch
    lstm_persist<<<NCTA, NTHR, lstm_smem>>>(
        pre_enc, pre_dec,
        enc_W + (size_t)DD * G4, dec_W + (size_t)DD * G4,
        len_enc, len_dec, hbuf, hs, scnt);

    // (5..) zero invalid output rows, then the projection chain
    zero_invalid<<<dim3(32, BSZ * TY), 256>>>(len_dec, out);
    transpose_f16<<<dim3(VV / 32, DD / 32), 256>>>(proj_W, VV, Bt_h);
    compact_f16<<<(BSZ * TY * DD) / 256, 256>>>(hs, map, Ah_h);
    mma_gemm_h1<<<dim3(16, VV / 128), 256, gemm1_smem>>>(Ah_h, Bt_h,
                                                         out, VV, map, nvalid);
}

// round 17
// speedup vs baseline: 1.1868x; 1.0020x over previous
#include <cuda_runtime.h>
#include <cuda_bf16.h>
#include <cuda_fp16.h>
#include <math.h>
#include <stdint.h>

// Problem constants
#define BSZ 32
#define TX  64
#define TY  64
#define DD  512
#define HH  512
#define G4  2048   // 4*H
#define VV  32000

#define NCTA 128   // persistent LSTM CTAs
#define NTHR 256

// ---------------- scratch (device globals; no allocation allowed) ----------------
__device__ float g_pre_enc[TX * BSZ * G4];
__device__ float g_pre_dec[TY * BSZ * G4];
__device__ float g_hbuf[2][BSZ * HH];
__device__ float g_hs[BSZ * TY * HH];
__device__ unsigned g_scnt[TX + TY];   // per-step arrival counters
__device__ int g_map[BSZ * TY];        // projection: compact row -> b*64+t, -1 = pad
__device__ int g_mapE[BSZ * TX];       // enc preact: compact row -> t*32+b, -1 = pad
__device__ int g_mapD[BSZ * TY];       // dec preact: compact row -> t*32+b, -1 = pad
__device__ int g_nvalid[3];            // [0]=proj rows, [1]=enc rows, [2]=dec rows

// bf16 3-term operands for the pre-activation GEMMs (K-major, K=512)
__device__ __nv_bfloat16 g_WeT_hi[G4 * DD], g_WeT_lo[G4 * DD];
__device__ __nv_bfloat16 g_WdT_hi[G4 * DD], g_WdT_lo[G4 * DD];
__device__ __nv_bfloat16 g_Ae_hi[TX * BSZ * DD], g_Ae_lo[TX * BSZ * DD];   // compact rows
__device__ __nv_bfloat16 g_Ad_hi[TY * BSZ * DD], g_Ad_lo[TY * BSZ * DD];   // compact rows

// fp16 1-term operands for the projection GEMM
__device__ __half g_Bt_h[VV * DD];
__device__ __half g_Ah_h[BSZ * TY * DD];

// ======================= helpers =======================
__device__ __forceinline__ uint32_t smem_u32(const void* p) {
    uint32_t a;
    asm("{ .reg .u64 t; cvta.to.shared.u64 t, %1; cvt.u32.u64 %0, t; }" : "=r"(a) : "l"(p));
    return a;
}

#define LDSM4(r, addr) \
    asm volatile("ldmatrix.sync.aligned.m8n8.x4.shared.b16 {%0,%1,%2,%3}, [%4];" \
        : "=r"((r)[0]), "=r"((r)[1]), "=r"((r)[2]), "=r"((r)[3]) : "r"(addr))

#define MMA_BF16(d, a, b0, b1) \
    asm volatile("mma.sync.aligned.m16n8k16.row.col.f32.bf16.bf16.f32 " \
        "{%0,%1,%2,%3}, {%4,%5,%6,%7}, {%8,%9}, {%0,%1,%2,%3};" \
        : "+f"((d)[0]), "+f"((d)[1]), "+f"((d)[2]), "+f"((d)[3]) \
        : "r"((a)[0]), "r"((a)[1]), "r"((a)[2]), "r"((a)[3]), "r"(b0), "r"(b1))

#define MMA_F16(d, a, b0, b1) \
    asm volatile("mma.sync.aligned.m16n8k16.row.col.f32.f16.f16.f32 " \
        "{%0,%1,%2,%3}, {%4,%5,%6,%7}, {%8,%9}, {%0,%1,%2,%3};" \
        : "+f"((d)[0]), "+f"((d)[1]), "+f"((d)[2]), "+f"((d)[3]) \
        : "r"((a)[0]), "r"((a)[1]), "r"((a)[2]), "r"((a)[3]), "r"(b0), "r"(b1))

#define CP_ASYNC16(dst, src) \
    asm volatile("cp.async.cg.shared.global [%0], [%1], 16;" :: "r"(dst), "l"(src))
#define CP_COMMIT()  asm volatile("cp.async.commit_group;" ::: "memory")
#define CP_WAIT(n)   asm volatile("cp.async.wait_group %0;" :: "n"(n) : "memory")

// packed f32x2 FMA (Blackwell base ISA)
__device__ __forceinline__ void fma2(uint64_t& d, uint64_t a, uint64_t b) {
    asm("fma.rn.f32x2 %0, %1, %2, %0;" : "+l"(d) : "l"(a), "l"(b));
}
__device__ __forceinline__ float pairsum(uint64_t v) {
    return __uint_as_float((uint32_t)v) + __uint_as_float((uint32_t)(v >> 32));
}

// =====================================================================
// Fused init: zero h state + step counters; block 0 builds all three
// compact maps.
// =====================================================================
__global__ void zero_init(float* __restrict__ hbuf, unsigned* __restrict__ scnt,
                          const int* __restrict__ len_enc, const int* __restrict__ len_dec,
                          int* __restrict__ map, int* __restrict__ mapE,
                          int* __restrict__ mapD, int* __restrict__ nvalid)
{
    const int i = blockIdx.x * 256 + threadIdx.x;
    if (i < BSZ * HH) hbuf[i] = 0.f;
    if (i < TX + TY)  scnt[i] = 0u;

    if (blockIdx.x == 0) {
        __shared__ int offP[BSZ], offE[BSZ], offD[BSZ];
        const int tid = threadIdx.x;
        if (tid == 0) {
            int aP = 0, aE = 0, aD = 0;
            for (int b = 0; b < BSZ; b++) {
                int Ld = len_dec[b]; if (Ld < 0) Ld = 0; if (Ld > TY) Ld = TY;
                int Le = len_enc[b]; if (Le < 0) Le = 0; if (Le > TX) Le = TX;
                offP[b] = aP; aP += Ld;
                offE[b] = aE; aE += Le;
                offD[b] = aD; aD += Ld;
            }
            nvalid[0] = aP;
            nvalid[1] = aE;
            nvalid[2] = aD;
        }
        __syncthreads();
        for (int j = tid; j < BSZ * TY; j += 256) { map[j] = -1; mapD[j] = -1; }
        for (int j = tid; j < BSZ * TX; j += 256) mapE[j] = -1;
        __syncthreads();
        for (int b = 0; b < BSZ; b++) {
            int Ld = len_dec[b]; if (Ld > TY) Ld = TY;
            int Le = len_enc[b]; if (Le > TX) Le = TX;
            for (int t = tid; t < Ld; t += 256) {
                map[offP[b] + t]  = b * TY + t;      // projection (hs row id)
                mapD[offD[b] + t] = t * BSZ + b;     // dec preact (pre row id)
            }
            for (int t = tid; t < Le; t += 256)
                mapE[offE[b] + t] = t * BSZ + b;     // enc preact (pre row id)
        }
    }
}

// =====================================================================
// Fused prep: z=0,1 -> Wx transpose+split (enc/dec); z=2,3 -> embedding
// gather+split into COMPACT rows via mapE/mapD (pad rows zeroed).
// =====================================================================
__global__ void prep(const float* __restrict__ enc_W, const float* __restrict__ dec_W,
                     __nv_bfloat16* __restrict__ WeT_hi, __nv_bfloat16* __restrict__ WeT_lo,
                     __nv_bfloat16* __restrict__ WdT_hi, __nv_bfloat16* __restrict__ WdT_lo,
                     const float* __restrict__ E,
                     const int* __restrict__ idsE, const int* __restrict__ idsD,
                     const int* __restrict__ mapE, const int* __restrict__ mapD,
                     __nv_bfloat16* __restrict__ Ae_hi, __nv_bfloat16* __restrict__ Ae_lo,
                     __nv_bfloat16* __restrict__ Ad_hi, __nv_bfloat16* __restrict__ Ad_lo)
{
    const int z = blockIdx.z;
    if (z < 2) {
        if (blockIdx.x >= (G4 / 32) * (DD / 32)) return;   // 64*16 = 1024 tiles
        const float* src = z ? dec_W : enc_W;
        __nv_bfloat16* hi = z ? WdT_hi : WeT_hi;
        __nv_bfloat16* lo = z ? WdT_lo : WeT_lo;

        __shared__ float t[32][33];
        const int tx = threadIdx.x & 31, ty = threadIdx.x >> 5;
        const int bx = blockIdx.x & 63, by = blockIdx.x >> 6;
        const int n = bx * 32 + tx;
        const int kb = by * 32;
#pragma unroll
        for (int r = 0; r < 32; r += 8)
            t[ty + r][tx] = src[(size_t)(kb + ty + r) * G4 + n];
        __syncthreads();
#pragma unroll
        for (int r = 0; r < 32; r += 8) {
            const int nn = bx * 32 + ty + r;
            const int kk = kb + tx;
            const float v = t[tx][ty + r];
            const __nv_bfloat16 h = __float2bfloat16(v);
            hi[(size_t)nn * DD + kk] = h;
            lo[(size_t)nn * DD + kk] = __float2bfloat16(v - __bfloat162float(h));
        }
    } else {
        const int* ids = (z == 3) ? idsD : idsE;
        const int* mp  = (z == 3) ? mapD : mapE;
        __nv_bfloat16* hi = (z == 3) ? Ad_hi : Ae_hi;
        __nv_bfloat16* lo = (z == 3) ? Ad_lo : Ae_lo;
        const int idxT = (z == 3) ? TY : TX;

        const int i = blockIdx.x * 256 + threadIdx.x;
        const int j = i >> 9, k = i & 511;
        const int m = mp[j];                   // original row t*32+b, or -1
        float v = 0.f;
        if (m >= 0) {
            const int b = m & 31, t = m >> 5;
            v = E[(size_t)ids[b * idxT + t] * DD + k];
        }
        const __nv_bfloat16 h = __float2bfloat16(v);
        hi[i] = h;
        lo[i] = __float2bfloat16(v - __bfloat162float(h));
    }
}

// =====================================================================
// Fused 3-term split-bf16 GEMM for BOTH pre-activations (z = 0 enc, 1 dec),
// M-compacted: CTAs past nvalid exit; C rows scatter through the map.
// =====================================================================
__global__ __launch_bounds__(256, 1)
void mma_gemm_pre(const __nv_bfloat16* __restrict__ AhiE, const __nv_bfloat16* __restrict__ AloE,
                  const __nv_bfloat16* __restrict__ BhiE, const __nv_bfloat16* __restrict__ BloE,
                  const float* __restrict__ biasE, float* __restrict__ CE,
                  const __nv_bfloat16* __restrict__ AhiD, const __nv_bfloat16* __restrict__ AloD,
                  const __nv_bfloat16* __restrict__ BhiD, const __nv_bfloat16* __restrict__ BloD,
                  const float* __restrict__ biasD, float* __restrict__ CD,
                  const int* __restrict__ mapE, const int* __restrict__ mapD,
                  const int* __restrict__ nvalid)
{
    const int m0 = blockIdx.x * 128;
    if (m0 >= nvalid[1 + blockIdx.z]) return;

    const __nv_bfloat16* Ahi = blockIdx.z ? AhiD : AhiE;
    const __nv_bfloat16* Alo = blockIdx.z ? AloD : AloE;
    const __nv_bfloat16* Bhi = blockIdx.z ? BhiD : BhiE;
    const __nv_bfloat16* Blo = blockIdx.z ? BloD : BloE;
    const float* bias = blockIdx.z ? biasD : biasE;
    float* C = blockIdx.z ? CD : CE;
    const int* mp = blockIdx.z ? mapD : mapE;
    const int N = G4;

    extern __shared__ char smc[];
    const uint32_t sbase = smem_u32(smc);

    const int tid  = threadIdx.x;
    const int wid  = tid >> 5;
    const int lane = tid & 31;
    const int n0 = blockIdx.y * 128;
    const int wm = (wid & 3) * 32;
    const int wn = (wid >> 2) * 64;

    const __nv_bfloat16* srcs[4] = { Ahi, Alo, Bhi, Blo };
    const int rb[4] = { m0, m0, n0, n0 };

    uint32_t dsts[4];
    const __nv_bfloat16* gsrc[4][4];
#pragma unroll
    for (int q = 0; q < 4; q++) {
        const int i = tid + q * 256;
        const int r = i >> 3, u = i & 7;
        dsts[q] = (uint32_t)(r * 128 + ((u ^ (r & 7)) << 4));
#pragma unroll
        for (int t4 = 0; t4 < 4; t4++)
            gsrc[t4][q] = srcs[t4] + (size_t)(rb[t4] + r) * DD + u * 8;
    }

    float acc[2][8][4];
#pragma unroll
    for (int mt = 0; mt < 2; mt++)
#pragma unroll
        for (int nt = 0; nt < 8; nt++)
#pragma unroll
            for (int e = 0; e < 4; e++) acc[mt][nt][e] = 0.f;

#pragma unroll
    for (int s = 0; s < 2; s++) {
        const uint32_t sb = sbase + (uint32_t)s * 65536u;
        const int koff = s * 64;
#pragma unroll
        for (int t4 = 0; t4 < 4; t4++)
#pragma unroll
            for (int q = 0; q < 4; q++)
                CP_ASYNC16(sb + t4 * 16384 + dsts[q], gsrc[t4][q] + koff);
        CP_COMMIT();
    }

    const int lrow15 = lane & 15;
    const int lhalf  = lane >> 4;

    int cs = 0;
    for (int it = 0; it < 8; it++) {
        if (it < 7) { CP_WAIT(1); } else { CP_WAIT(0); }
        __syncthreads();

        if (it + 2 < 8) {
            int ps = cs + 2; if (ps >= 3) ps -= 3;
            const uint32_t sb = sbase + (uint32_t)ps * 65536u;
            const int koff = (it + 2) * 64;
#pragma unroll
            for (int t4 = 0; t4 < 4; t4++)
#pragma unroll
                for (int q = 0; q < 4; q++)
                    CP_ASYNC16(sb + t4 * 16384 + dsts[q], gsrc[t4][q] + koff);
            CP_COMMIT();
        }

        const uint32_t B = sbase + (uint32_t)cs * 65536u;

#pragma unroll
        for (int j = 0; j < 4; j++) {
            uint32_t ah[2][4], al[2][4];
            uint32_t bh[4][4], bl[4][4];
#pragma unroll
            for (int mt = 0; mt < 2; mt++) {
                const int row = wm + mt * 16 + lrow15;
                const int unit = j * 2 + lhalf;
                const uint32_t addr = B + row * 128 + (((unit ^ (row & 7))) << 4);
                LDSM4(ah[mt], addr);
                LDSM4(al[mt], addr + 16384);
            }
#pragma unroll
            for (int g = 0; g < 4; g++) {
                const int row = wn + g * 16 + lrow15;
                const int unit = j * 2 + lhalf;
                const uint32_t addr = B + 32768 + row * 128 + (((unit ^ (row & 7))) << 4);
                LDSM4(bh[g], addr);
                LDSM4(bl[g], addr + 16384);
            }
#pragma unroll
            for (int mt = 0; mt < 2; mt++)
#pragma unroll
                for (int nt = 0; nt < 8; nt++) {
                    const int g = nt >> 1, o = nt & 1;
                    MMA_BF16(acc[mt][nt], ah[mt], bh[g][o], bh[g][o + 2]);
                    MMA_BF16(acc[mt][nt], ah[mt], bl[g][o], bl[g][o + 2]);
                    MMA_BF16(acc[mt][nt], al[mt], bh[g][o], bh[g][o + 2]);
                }
        }
        cs++; if (cs == 3) cs = 0;
    }

    const int erow = wm + (lane >> 2);
    const int ec = n0 + wn + (lane & 3) * 2;
#pragma unroll
    for (int mt = 0; mt < 2; mt++) {
        const int r0 = m0 + erow + mt * 16;
        const int r1 = r0 + 8;
        const int o0 = mp[r0];
        const int o1 = mp[r1];
#pragma unroll
        for (int nt = 0; nt < 8; nt++) {
            const int col = ec + nt * 8;
            const float b0 = bias[col], b1 = bias[col + 1];
            if (o0 >= 0) {
                float* p0 = C + (size_t)o0 * N + col;
                p0[0] = acc[mt][nt][0] + b0;
                p0[1] = acc[mt][nt][1] + b1;
            }
            if (o1 >= 0) {
                float* p1 = C + (size_t)o1 * N + col;
                p1[0] = acc[mt][nt][2] + b0;
                p1[1] = acc[mt][nt][3] + b1;
            }
        }
    }
}

// =====================================================================
// 1-term fp16 GEMM (projection): C = fp16(A) @ fp16(B)^T, compacted.
// =====================================================================
__global__ __launch_bounds__(256, 1)
void mma_gemm_h1(const __half* __restrict__ Ah, const __half* __restrict__ Bh,
                 float* __restrict__ C, int N,
                 const int* __restrict__ map, const int* __restrict__ nvalidp)
{
    const int m0 = blockIdx.x * 128;
    const int n0 = blockIdx.y * 128;
    if (m0 >= *nvalidp) return;

    extern __shared__ char smc[];
    const uint32_t sbase = smem_u32(smc);

    const int tid  = threadIdx.x;
    const int wid  = tid >> 5;
    const int lane = tid & 31;
    const int wm = (wid & 3) * 32;
    const int wn = (wid >> 2) * 64;

    const __half* srcs[2] = { Ah, Bh };
    const int rb[2] = { m0, n0 };

    uint32_t dsts[4];
    const __half* gsrc[2][4];
#pragma unroll
    for (int q = 0; q < 4; q++) {
        const int i = tid + q * 256;
        const int r = i >> 3, u = i & 7;
        dsts[q] = (uint32_t)(r * 128 + ((u ^ (r & 7)) << 4));
#pragma unroll
        for (int t2 = 0; t2 < 2; t2++)
            gsrc[t2][q] = srcs[t2] + (size_t)(rb[t2] + r) * DD + u * 8;
    }

    float acc[2][8][4];
#pragma unroll
    for (int mt = 0; mt < 2; mt++)
#pragma unroll
        for (int nt = 0; nt < 8; nt++)
#pragma unroll
            for (int e = 0; e < 4; e++) acc[mt][nt][e] = 0.f;

#pragma unroll
    for (int s = 0; s < 2; s++) {
        const uint32_t sb = sbase + (uint32_t)s * 32768u;
        const int koff = s * 64;
#pragma unroll
        for (int t2 = 0; t2 < 2; t2++)
#pragma unroll
            for (int q = 0; q < 4; q++)
                CP_ASYNC16(sb + t2 * 16384 + dsts[q], gsrc[t2][q] + koff);
        CP_COMMIT();
    }

    const int lrow15 = lane & 15;
    const int lhalf  = lane >> 4;

    int cs = 0;
    for (int it = 0; it < 8; it++) {
        if (it < 7) { CP_WAIT(1); } else { CP_WAIT(0); }
        __syncthreads();

        if (it + 2 < 8) {
            int ps = cs + 2; if (ps >= 3) ps -= 3;
            const uint32_t sb = sbase + (uint32_t)ps * 32768u;
            const int koff = (it + 2) * 64;
#pragma unroll
            for (int t2 = 0; t2 < 2; t2++)
#pragma unroll
                for (int q = 0; q < 4; q++)
                    CP_ASYNC16(sb + t2 * 16384 + dsts[q], gsrc[t2][q] + koff);
            CP_COMMIT();
        }

        const uint32_t B = sbase + (uint32_t)cs * 32768u;

#pragma unroll
        for (int j = 0; j < 4; j++) {
            uint32_t ah[2][4];
            uint32_t bh[4][4];
#pragma unroll
            for (int mt = 0; mt < 2; mt++) {
                const int row = wm + mt * 16 + lrow15;
                const int unit = j * 2 + lhalf;
                LDSM4(ah[mt], B + row * 128 + (((unit ^ (row & 7))) << 4));
            }
#pragma unroll
            for (int g = 0; g < 4; g++) {
                const int row = wn + g * 16 + lrow15;
                const int unit = j * 2 + lhalf;
                LDSM4(bh[g], B + 16384 + row * 128 + (((unit ^ (row & 7))) << 4));
            }
#pragma unroll
            for (int mt = 0; mt < 2; mt++)
#pragma unroll
                for (int nt = 0; nt < 8; nt++) {
                    const int g = nt >> 1, o = nt & 1;
                    MMA_F16(acc[mt][nt], ah[mt], bh[g][o], bh[g][o + 2]);
                }
        }
        cs++; if (cs == 3) cs = 0;
    }

    const int erow = wm + (lane >> 2);
    const int ec = n0 + wn + (lane & 3) * 2;
#pragma unroll
    for (int mt = 0; mt < 2; mt++) {
        const int r0 = m0 + erow + mt * 16;
        const int r1 = r0 + 8;
        const int o0 = map[r0];
        const int o1 = map[r1];
#pragma unroll
        for (int nt = 0; nt < 8; nt++) {
            const int col = ec + nt * 8;
            if (o0 >= 0) {
                float* p0 = C + (size_t)o0 * N + col;
                p0[0] = acc[mt][nt][0];
                p0[1] = acc[mt][nt][1];
            }
            if (o1 >= 0) {
                float* p1 = C + (size_t)o1 * N + col;
                p1[0] = acc[mt][nt][2];
                p1[1] = acc[mt][nt][3];
            }
        }
    }
}

// Zero only the invalid output rows (t >= len_dec[b]).
__global__ void zero_invalid(const int* __restrict__ len_dec, float* __restrict__ out)
{
    const int row = blockIdx.y;          // b*64 + t
    const int b = row >> 6, t = row & 63;
    if (t < len_dec[b]) return;
    const int i = blockIdx.x * 1024 + threadIdx.x * 4;
    if (i < VV) {
        float4 z = make_float4(0.f, 0.f, 0.f, 0.f);
        *(float4*)(out + (size_t)row * VV + i) = z;
    }
}

// Compact hs into fp16 (single term).
__global__ void compact_f16(const float* __restrict__ src,
                            const int* __restrict__ map,
                            __half* __restrict__ dst)
{
    const int i = blockIdx.x * 256 + threadIdx.x;
    const int j = i >> 9, k = i & 511;
    const int s = map[j];
    const float v = (s >= 0) ? src[(size_t)s * DD + k] : 0.f;
    dst[i] = __float2half(v);
}

// Transpose + fp16:  src[K=512][VV] f32  ->  h [VV][512] fp16
__global__ void transpose_f16(const float* __restrict__ src, int N,
                              __half* __restrict__ dst)
{
    __shared__ float t[32][33];
    const int tx = threadIdx.x & 31, ty = threadIdx.x >> 5;
    const int n = blockIdx.x * 32 + tx;
    const int kb = blockIdx.y * 32;
#pragma unroll
    for (int r = 0; r < 32; r += 8)
        t[ty + r][tx] = src[(size_t)(kb + ty + r) * N + n];
    __syncthreads();
#pragma unroll
    for (int r = 0; r < 32; r += 8) {
        const int nn = blockIdx.x * 32 + ty + r;
        const int kk = kb + tx;
        dst[(size_t)nn * DD + kk] = __float2half(t[tx][ty + r]);
    }
}

// =====================================================================
// Persistent LSTM — PROVEN R13 version verbatim.
// =====================================================================
__global__ __launch_bounds__(NTHR, 1)
void lstm_persist(const float* __restrict__ pre_enc, const float* __restrict__ pre_dec,
                  const float* __restrict__ enc_Wh, const float* __restrict__ dec_Wh,
                  const int* __restrict__ len_enc, const int* __restrict__ len_dec,
                  float* __restrict__ hbuf, float* __restrict__ hs,
                  unsigned* __restrict__ scnt)
{
    extern __shared__ float smf[];
    float* whs  = smf;                    // 16*516
    float* hsm  = smf + 16 * 516;         // 32*516
    float* zbuf = hsm + 32 * 516;         // 2 * 544

    const int tid = threadIdx.x;
    const int cta = blockIdx.x;
    const int wid = tid >> 5;
    const int lane = tid & 31;

    // dot decomposition
    const int wk = wid >> 2;
    const int wq = wid & 3;
    const int base_b = (wq & 1) * 16;
    const int base_z = (wq >> 1) * 8;
    const int lb = lane & 7;
    const int lz = lane >> 3;
    const int rb0 = base_b + lb,     rb1 = base_b + 8 + lb;
    const int rz0 = base_z + lz,     rz1 = base_z + 4 + lz;
    const int kof = wk * 256;

    // gate-phase constants (tid < 128)
    const int gb  = tid >> 2;
    const int ghc = tid & 3;
    const int gn  = cta * 4 + ghc;

    float c_reg = 0.f;
    float pzi = 0.f, pzj = 0.f, pzf = 0.f, pzo = 0.f;

    for (int phase = 0; phase < 2; phase++) {
        const float* Wh  = phase ? dec_Wh  : enc_Wh;
        const float* pre = phase ? pre_dec : pre_enc;
        const int*   len = phase ? len_dec : len_enc;

        for (int i = tid; i < 16 * 512; i += NTHR) {
            int z = i >> 9, k = i & 511;
            whs[z * 516 + k] =
                __ldg(&Wh[(size_t)k * G4 + (z >> 2) * 512 + cta * 4 + (z & 3)]);
        }
        const int mylen = (tid < 128) ? len[gb] : 0;

        // prefetch pz for s = 0
        if (tid < 128) {
            const float* pz = pre + (size_t)gb * G4 + gn;
            pzi = __ldg(pz);
            pzj = __ldg(pz + 512);
            pzf = __ldg(pz + 1024);
            pzo = __ldg(pz + 1536);
        }
        __syncthreads();

        for (int s = 0; s < 64; s++) {
            const int sigma = phase * 64 + s;
            const float* hin  = hbuf + (sigma & 1) * (BSZ * HH);
            float*       hout = hbuf + ((sigma + 1) & 1) * (BSZ * HH);

            // Stage h into smem (uniform; fully unrolled for max MLP).
#pragma unroll
            for (int q = 0; q < 16; q++) {
                const int i = tid + q * NTHR;
                const int b = i >> 7, k4 = i & 127;
                float4 v = __ldcg((const float4*)&hin[b * HH + k4 * 4]);
                *(float4*)&hsm[b * 516 + k4 * 4] = v;
            }
            __syncthreads();

            // 2b x 2zc register tile over this warp's k-half.
            {
                const float* A0 = &hsm[rb0 * 516 + kof];
                const float* A1 = &hsm[rb1 * 516 + kof];
                const float* W0 = &whs[rz0 * 516 + kof];
                const float* W1 = &whs[rz1 * 516 + kof];
                uint64_t a00 = 0, a01 = 0, a10 = 0, a11 = 0;
#pragma unroll 4
                for (int k = 0; k < 256; k += 4) {
                    const ulonglong2 va0 = *(const ulonglong2*)(A0 + k);
                    const ulonglong2 va1 = *(const ulonglong2*)(A1 + k);
                    const ulonglong2 vw0 = *(const ulonglong2*)(W0 + k);
                    const ulonglong2 vw1 = *(const ulonglong2*)(W1 + k);
                    fma2(a00, va0.x, vw0.x); fma2(a00, va0.y, vw0.y);
                    fma2(a01, va0.x, vw1.x); fma2(a01, va0.y, vw1.y);
                    fma2(a10, va1.x, vw0.x); fma2(a10, va1.y, vw0.y);
                    fma2(a11, va1.x, vw1.x); fma2(a11, va1.y, vw1.y);
                }
                float* zb = zbuf + wk * 544;
                zb[rb0 * 17 + rz0] = pairsum(a00);
                zb[rb0 * 17 + rz1] = pairsum(a01);
                zb[rb1 * 17 + rz0] = pairsum(a10);
                zb[rb1 * 17 + rz1] = pairsum(a11);
            }
            __syncthreads();

            if (tid < 128) {
                const int zi0 = gb * 17 + ghc;
                float zi = pzi + zbuf[zi0]      + zbuf[544 + zi0];
                float zj = pzj + zbuf[zi0 + 4]  + zbuf[544 + zi0 + 4];
                float zf = pzf + zbuf[zi0 + 8]  + zbuf[544 + zi0 + 8];
                float zo = pzo + zbuf[zi0 + 12] + zbuf[544 + zi0 + 12];

                float fg = 1.f / (1.f + expf(-(zf + 1.0f)));   // forget bias 1.0
                float ig = 1.f / (1.f + expf(-zi));
                float og = 1.f / (1.f + expf(-zo));
                float cn = c_reg * fg + ig * tanhf(zj);
                float hn = tanhf(cn) * og;

                bool m = (s < mylen);
                float hprev = hsm[gb * 516 + gn];
                c_reg = m ? cn : c_reg;
                hout[gb * HH + gn] = m ? hn : hprev;
                if (phase)
                    hs[((size_t)gb * TY + s) * HH + gn] = m ? hn : 0.f;
            }
            __syncthreads();   // all h stores issued before arrival

            // prefetch pz for step s+1 (off the post-barrier critical path)
            if (tid < 128 && s + 1 < 64) {
                const float* pz = pre + (size_t)(s + 1) * BSZ * G4 + (size_t)gb * G4 + gn;
                pzi = __ldg(pz);
                pzj = __ldg(pz + 512);
                pzf = __ldg(pz + 1024);
                pzo = __ldg(pz + 1536);
            }

            if (tid == 0) {
                unsigned* ctr = scnt + sigma;
                asm volatile("red.release.gpu.global.add.u32 [%0], 1;"
                             :: "l"(ctr) : "memory");
                unsigned v;
                do {
                    asm volatile("ld.relaxed.gpu.global.u32 %0, [%1];"
                                 : "=r"(v) : "l"(ctr) : "memory");
                } while (v < NCTA);
                asm volatile("ld.acquire.gpu.global.u32 %0, [%1];"
                             : "=r"(v) : "l"(ctr) : "memory");
            }
            __syncthreads();   // propagate tid0's acquire to the CTA
        }
    }
}

// =====================================================================
// Host launcher (graph-capturable). Side stream runs transpose_f16 +
// zero_invalid concurrently with the persistent LSTM (which leaves 20
// SMs and nearly all DRAM/L2 bandwidth idle); joined before the
// projection. Streams/events are host objects created once, outside
// capture (first call is the uncaptured correctness run).
// =====================================================================
extern "C" void kernel_launch(void* const* d_in, const int* in_sizes, int n_in,
                              void* d_out, int out_size)
{
    const int*   enc_ids = (const int*)d_in[0];
    const int*   dec_ids = (const int*)d_in[1];
    const int*   len_enc = (const int*)d_in[2];
    const int*   len_dec = (const int*)d_in[3];
    const float* E       = (const float*)d_in[4];
    const float* enc_W   = (const float*)d_in[5];
    const float* enc_b   = (const float*)d_in[6];
    const float* dec_W   = (const float*)d_in[7];
    const float* dec_b   = (const float*)d_in[8];
    const float* proj_W  = (const float*)d_in[9];
    float*       out     = (float*)d_out;

    float *pre_enc, *pre_dec, *hbuf, *hs;
    unsigned* scnt;
    int *map, *mapE, *mapD, *nvalid;
    cudaGetSymbolAddress((void**)&pre_enc, g_pre_enc);
    cudaGetSymbolAddress((void**)&pre_dec, g_pre_dec);
    cudaGetSymbolAddress((void**)&hbuf,    g_hbuf);
    cudaGetSymbolAddress((void**)&hs,      g_hs);
    cudaGetSymbolAddress((void**)&scnt,    g_scnt);
    cudaGetSymbolAddress((void**)&map,     g_map);
    cudaGetSymbolAddress((void**)&mapE,    g_mapE);
    cudaGetSymbolAddress((void**)&mapD,    g_mapD);
    cudaGetSymbolAddress((void**)&nvalid,  g_nvalid);

    __nv_bfloat16 *WeT_hi, *WeT_lo, *WdT_hi, *WdT_lo;
    __nv_bfloat16 *Ae_hi, *Ae_lo, *Ad_hi, *Ad_lo;
    __half *Bt_h, *Ah_h;
    cudaGetSymbolAddress((void**)&WeT_hi, g_WeT_hi);
    cudaGetSymbolAddress((void**)&WeT_lo, g_WeT_lo);
    cudaGetSymbolAddress((void**)&WdT_hi, g_WdT_hi);
    cudaGetSymbolAddress((void**)&WdT_lo, g_WdT_lo);
    cudaGetSymbolAddress((void**)&Ae_hi,  g_Ae_hi);
    cudaGetSymbolAddress((void**)&Ae_lo,  g_Ae_lo);
    cudaGetSymbolAddress((void**)&Ad_hi,  g_Ad_hi);
    cudaGetSymbolAddress((void**)&Ad_lo,  g_Ad_lo);
    cudaGetSymbolAddress((void**)&Bt_h,   g_Bt_h);
    cudaGetSymbolAddress((void**)&Ah_h,   g_Ah_h);

    const size_t lstm_smem  = (16 * 516 + 32 * 516 + 2 * 544) * sizeof(float);
    const size_t gemm_smem  = 3 * 4 * 16384;   // 192KB (bf16 3-term preact)
    const size_t gemm1_smem = 3 * 2 * 16384;   // 96KB (fp16 1-term proj)

    static bool init_done = false;
    static cudaStream_t s2;
    static cudaEvent_t evF, evJ;
    if (!init_done) {
        cudaFuncSetAttribute(lstm_persist,
                             cudaFuncAttributeMaxDynamicSharedMemorySize, (int)lstm_smem);
        cudaFuncSetAttribute(mma_gemm_pre,
                             cudaFuncAttributeMaxDynamicSharedMemorySize, (int)gemm_smem);
        cudaFuncSetAttribute(mma_gemm_h1,
                             cudaFuncAttributeMaxDynamicSharedMemorySize, (int)gemm1_smem);
        cudaStreamCreateWithFlags(&s2, cudaStreamNonBlocking);
        cudaEventCreateWithFlags(&evF, cudaEventDisableTiming);
        cudaEventCreateWithFlags(&evJ, cudaEventDisableTiming);
        init_done = true;
    }

    // ---- fork: independent bandwidth work on the side stream ----
    cudaEventRecord(evF, 0);
    cudaStreamWaitEvent(s2, evF, 0);
    transpose_f16<<<dim3(VV / 32, DD / 32), 256, 0, s2>>>(proj_W, VV, Bt_h);
    zero_invalid<<<dim3(32, BSZ * TY), 256, 0, s2>>>(len_dec, out);
    cudaEventRecord(evJ, s2);

    // ---- main stream: critical path ----
    // (1) zero h + step counters; build compact maps
    zero_init<<<64, 256>>>(hbuf, scnt, len_enc, len_dec, map, mapE, mapD, nvalid);

    // (2) fused Wx transposes + compact embedding gathers
    prep<<<dim3(4096, 1, 4), 256>>>(enc_W, dec_W, WeT_hi, WeT_lo, WdT_hi, WdT_lo,
                                    E, enc_ids, dec_ids, mapE, mapD,
                                    Ae_hi, Ae_lo, Ad_hi, Ad_lo);

    // (3) fused pre-activation GEMMs (enc & dec), M-compacted
    mma_gemm_pre<<<dim3(16, G4 / 128, 2), 256, gemm_smem>>>(
        Ae_hi, Ae_lo, WeT_hi, WeT_lo, enc_b, pre_enc,
        Ad_hi, Ad_lo, WdT_hi, WdT_lo, dec_b, pre_dec,
        mapE, mapD, nvalid);

    // (4) full recurrence (side-stream work overlaps this: 20 idle SMs,
    //     DRAM ~0.7% busy)
    lstm_persist<<<NCTA, NTHR, lstm_smem>>>(
        pre_enc, pre_dec,
        enc_W + (size_t)DD * G4, dec_W + (size_t)DD * G4,
        len_enc, len_dec, hbuf, hs, scnt);

    // (5) compact hs, join side stream (Bt_h ready), then projection
    compact_f16<<<(BSZ * TY * DD) / 256, 256>>>(hs, map, Ah_h);
    cudaStreamWaitEvent(0, evJ, 0);
    mma_gemm_h1<<<dim3(16, VV / 128), 256, gemm1_smem>>>(Ah_h, Bt_h,
                                                         out, VV, map, nvalid);
}